// round 12
// baseline (speedup 1.0000x reference)
#include <cuda_runtime.h>
#include <cuda_bf16.h>

#define NREF  4096
#define NIN   8192
#define DFEAT 512
#define PDIM  256

// ---- GEMM2 (bf16, round-9 proven path) constants ----
#define TILE_B   8192                       // 128 rows * 64B
#define STAGE_B  (4 * TILE_B)
#define NSTAGE   3
#define SMEM_TOTAL (NSTAGE * STAGE_B + 512)

// ---- GEMM1 (int8 IMMA) constants ----
#define G1_TILE_B  (128 * 64)               // 8KB (int8, 64B rows)
#define G1_STAGE   (4 * G1_TILE_B)          // 32KB: Dq0,Dq1,Xq0,Xq1
#define G1_NSTAGE  3
#define G1_SMEM    (G1_NSTAGE * G1_STAGE + 2048)

// ---------------- scratch (device globals) ----------------
__device__ signed char g_Xq0[NREF * DFEAT], g_Xq1[NREF * DFEAT];
__device__ signed char g_Dq0[NIN * DFEAT],  g_Dq1[NIN * DFEAT];
__device__ float g_sX[NREF], g_sD[NIN];
__device__ __nv_bfloat16 g_Ah[PDIM * NREF];
__device__ __nv_bfloat16 g_Al[PDIM * NREF];
__device__ __nv_bfloat16 g_Kth[(size_t)NIN * NREF];
__device__ __nv_bfloat16 g_Ktl[(size_t)NIN * NREF];
__device__ float g_P[2 * PDIM * NIN];

__device__ __forceinline__ unsigned sm32(const void* p) {
    unsigned r;
    asm("{.reg .u64 t; cvta.to.shared.u64 t, %1; cvt.u32.u64 %0, t;}" : "=r"(r) : "l"(p));
    return r;
}

#define LDSM4(r, addr)                                                           \
    asm volatile("ldmatrix.sync.aligned.m8n8.x4.shared.b16 {%0,%1,%2,%3}, [%4];" \
                 : "=r"((r)[0]), "=r"((r)[1]), "=r"((r)[2]), "=r"((r)[3])        \
                 : "r"(addr))

// 64B-row swizzled offset (works for bf16 32-elem rows and int8 64-elem rows)
__device__ __forceinline__ unsigned sw_addr(int row, int ch) {
    return row * 64 + ((ch ^ ((row >> 1) & 3)) << 4);
}

// =======================  GEMM1: int8 IMMA path  ===========================

__device__ __forceinline__ void imma(int* c, const unsigned* a, unsigned b0, unsigned b1) {
    asm volatile(
        "mma.sync.aligned.m16n8k32.row.col.s32.s8.s8.s32 "
        "{%0,%1,%2,%3}, {%4,%5,%6,%7}, {%8,%9}, {%0,%1,%2,%3};"
        : "+r"(c[0]), "+r"(c[1]), "+r"(c[2]), "+r"(c[3])
        : "r"(a[0]), "r"(a[1]), "r"(a[2]), "r"(a[3]), "r"(b0), "r"(b1));
}

// Load one 128x64 int8 tile (row stride DFEAT) with 512 threads, 1x16B each.
__device__ __forceinline__ void load_tile_i8(unsigned sbuf, const signed char* src,
                                             int rowBase, int kOff, int tid) {
    const int row = tid >> 2;
    const int ch  = tid & 3;
    const signed char* g = src + (size_t)(rowBase + row) * DFEAT + kOff + ch * 16;
    const unsigned s = sbuf + sw_addr(row, ch);
    asm volatile("cp.async.cg.shared.global [%0], [%1], 16;" :: "r"(s), "l"(g));
}

// One K=64 chunk: 32x32 warp tile, digits fused:
//   S1 += a0.b0 ;  S2 += a0.b1 + a1.b0
__device__ __forceinline__ void imma_k64(unsigned sA0, unsigned sA1,
                                         unsigned sB0, unsigned sB1,
                                         int warpM, int warpN, int lane,
                                         int (*S1)[4][4], int (*S2)[4][4]) {
#pragma unroll
    for (int h = 0; h < 2; h++) {
        unsigned A0[2][4], A1[2][4], B0[2][4], B1[2][4];
#pragma unroll
        for (int mi = 0; mi < 2; mi++) {
            const int r  = warpM * 32 + mi * 16 + (lane & 15);
            const int ch = h * 2 + (lane >> 4);
            const unsigned off = sw_addr(r, ch);
            LDSM4(A0[mi], sA0 + off);
            LDSM4(A1[mi], sA1 + off);
        }
#pragma unroll
        for (int g = 0; g < 2; g++) {
            const int r  = warpN * 32 + g * 16 + (lane & 15);
            const int ch = h * 2 + (lane >> 4);
            const unsigned off = sw_addr(r, ch);
            LDSM4(B0[g], sB0 + off);
            LDSM4(B1[g], sB1 + off);
        }
#pragma unroll
        for (int mi = 0; mi < 2; mi++)
#pragma unroll
            for (int nt = 0; nt < 4; nt++) {
                const int g = nt >> 1, s = nt & 1;
                imma(S1[mi][nt], A0[mi], B0[g][s], B0[g][s + 2]);
            }
#pragma unroll
        for (int mi = 0; mi < 2; mi++)
#pragma unroll
            for (int nt = 0; nt < 4; nt++) {
                const int g = nt >> 1, s = nt & 1;
                imma(S2[mi][nt], A0[mi], B1[g][s], B1[g][s + 2]);
            }
#pragma unroll
        for (int mi = 0; mi < 2; mi++)
#pragma unroll
            for (int nt = 0; nt < 4; nt++) {
                const int g = nt >> 1, s = nt & 1;
                imma(S2[mi][nt], A1[mi], B0[g][s], B0[g][s + 2]);
            }
    }
}

// GEMM1: Kt[j,i] = mask(Z[j]==Z_ref[i]) * (desc[j].X_ref[i])^expK
// 512 threads, 16 warps (4x4), warp tile 32x32, K-chunk 64, 3-stage pipeline.
__global__ __launch_bounds__(512, 1) void gemm1_imma(const int* __restrict__ Zq,
                                                     const int* __restrict__ Zx,
                                                     const int* __restrict__ expKp) {
    extern __shared__ char dynsm[];
    const int tid = threadIdx.x, lane = tid & 31, wid = tid >> 5;
    const int warpM = wid & 3, warpN = wid >> 2;
    const int iBase = blockIdx.x * 128;   // X rows (N side)
    const int jBase = blockIdx.y * 128;   // desc rows (M side)

    int*   Zcol = (int*)(dynsm + G1_NSTAGE * G1_STAGE);
    int*   Zd_s = Zcol + 128;
    float* sXs  = (float*)(Zd_s + 128);
    float* sDs  = sXs + 128;
    if (tid < 128) {
        Zcol[tid] = Zx[iBase + tid];
        sXs[tid]  = g_sX[iBase + tid];
    } else if (tid < 256) {
        const int t = tid - 128;
        Zd_s[t] = Zq[jBase + t];
        sDs[t]  = g_sD[jBase + t];
    }

    int S1[2][4][4], S2[2][4][4];
#pragma unroll
    for (int i = 0; i < 2; i++)
#pragma unroll
        for (int j = 0; j < 4; j++)
#pragma unroll
            for (int k = 0; k < 4; k++) { S1[i][j][k] = 0; S2[i][j][k] = 0; }

    unsigned st[G1_NSTAGE][4];
#pragma unroll
    for (int s = 0; s < G1_NSTAGE; s++)
#pragma unroll
        for (int t = 0; t < 4; t++)
            st[s][t] = sm32(dynsm + s * G1_STAGE + t * G1_TILE_B);

#pragma unroll
    for (int s = 0; s < 2; s++) {
        load_tile_i8(st[s][0], g_Dq0, jBase, s * 64, tid);
        load_tile_i8(st[s][1], g_Dq1, jBase, s * 64, tid);
        load_tile_i8(st[s][2], g_Xq0, iBase, s * 64, tid);
        load_tile_i8(st[s][3], g_Xq1, iBase, s * 64, tid);
        asm volatile("cp.async.commit_group;" ::: "memory");
    }

    const int NITER = DFEAT / 64;       // 8
    for (int it = 0; it < NITER; it++) {
        asm volatile("cp.async.wait_group 1;" ::: "memory");
        __syncthreads();
        if (it + 2 < NITER) {
            const int s = (it + 2) % G1_NSTAGE, kOff = (it + 2) * 64;
            load_tile_i8(st[s][0], g_Dq0, jBase, kOff, tid);
            load_tile_i8(st[s][1], g_Dq1, jBase, kOff, tid);
            load_tile_i8(st[s][2], g_Xq0, iBase, kOff, tid);
            load_tile_i8(st[s][3], g_Xq1, iBase, kOff, tid);
        }
        asm volatile("cp.async.commit_group;" ::: "memory");
        const int b = it % G1_NSTAGE;
        imma_k64(st[b][0], st[b][1], st[b][2], st[b][3], warpM, warpN, lane, S1, S2);
    }

    // epilogue: reconstruct dot, pow, mask, bf16 hi/lo split, store K^T
    const int e = expKp[0];
    const float inv256 = 1.0f / 256.0f;
#pragma unroll
    for (int mi = 0; mi < 2; mi++) {
        const int r0 = warpM * 32 + mi * 16 + (lane >> 2);
        const int zr0 = Zd_s[r0], zr1 = Zd_s[r0 + 8];
        const float sa0 = sDs[r0], sa1 = sDs[r0 + 8];
        const size_t ro0 = (size_t)(jBase + r0) * NREF;
        const size_t ro1 = (size_t)(jBase + r0 + 8) * NREF;
#pragma unroll
        for (int nt = 0; nt < 4; nt++) {
            const int colL = warpN * 32 + nt * 8 + 2 * (lane & 3);
            const int zc0 = Zcol[colL], zc1 = Zcol[colL + 1];
            const float sb0 = sXs[colL], sb1 = sXs[colL + 1];
            float v0 = sa0 * sb0 * ((float)S1[mi][nt][0] + (float)S2[mi][nt][0] * inv256);
            float v1 = sa0 * sb1 * ((float)S1[mi][nt][1] + (float)S2[mi][nt][1] * inv256);
            float v2 = sa1 * sb0 * ((float)S1[mi][nt][2] + (float)S2[mi][nt][2] * inv256);
            float v3 = sa1 * sb1 * ((float)S1[mi][nt][3] + (float)S2[mi][nt][3] * inv256);
            float p0 = 1.f, p1 = 1.f, p2 = 1.f, p3 = 1.f;
            for (int t = 0; t < e; t++) { p0 *= v0; p1 *= v1; p2 *= v2; p3 *= v3; }
            if (zr0 != zc0) p0 = 0.f;
            if (zr0 != zc1) p1 = 0.f;
            if (zr1 != zc0) p2 = 0.f;
            if (zr1 != zc1) p3 = 0.f;

            __nv_bfloat16 h0 = __float2bfloat16(p0), h1 = __float2bfloat16(p1);
            __nv_bfloat16 h2 = __float2bfloat16(p2), h3 = __float2bfloat16(p3);
            __nv_bfloat162 hh01, hh23, ll01, ll23;
            hh01.x = h0; hh01.y = h1;
            hh23.x = h2; hh23.y = h3;
            ll01.x = __float2bfloat16(p0 - __bfloat162float(h0));
            ll01.y = __float2bfloat16(p1 - __bfloat162float(h1));
            ll23.x = __float2bfloat16(p2 - __bfloat162float(h2));
            ll23.y = __float2bfloat16(p3 - __bfloat162float(h3));

            const size_t cg = (size_t)iBase + colL;
            *(__nv_bfloat162*)(g_Kth + ro0 + cg) = hh01;
            *(__nv_bfloat162*)(g_Kth + ro1 + cg) = hh23;
            *(__nv_bfloat162*)(g_Ktl + ro0 + cg) = ll01;
            *(__nv_bfloat162*)(g_Ktl + ro1 + cg) = ll23;
        }
    }
}

// Row quantizer CORE: per-row scale + 2 int8 digits (delta1 = delta0/256).
// NOTE: destination device globals are referenced from DEVICE code only —
// passing __device__ symbols as host-side kernel args silently resolves to the
// host shadow address (ATS makes the write "succeed" into host memory).
__device__ __forceinline__ void quant_row_core(const float* __restrict__ src,
                                               signed char* __restrict__ q0,
                                               signed char* __restrict__ q1,
                                               float* __restrict__ scale,
                                               int row, int lane) {
    const float* rp = src + (size_t)row * DFEAT;
    float4 v[4];
    float m = 0.f;
#pragma unroll
    for (int i = 0; i < 4; i++) {
        v[i] = ((const float4*)rp)[lane * 4 + i];
        m = fmaxf(m, fmaxf(fmaxf(fabsf(v[i].x), fabsf(v[i].y)),
                           fmaxf(fabsf(v[i].z), fabsf(v[i].w))));
    }
#pragma unroll
    for (int o = 16; o; o >>= 1) m = fmaxf(m, __shfl_xor_sync(0xffffffffu, m, o));
    m = fmaxf(m, 1e-20f);
    const float d0s  = m * (1.0f / 127.0f);
    const float inv0 = 127.0f / m;
    if (lane == 0) scale[row] = d0s;

    signed char b0[16], b1[16];
#pragma unroll
    for (int i = 0; i < 4; i++) {
        float xs[4] = {v[i].x, v[i].y, v[i].z, v[i].w};
#pragma unroll
        for (int j = 0; j < 4; j++) {
            float x = xs[j];
            float d0 = fminf(fmaxf(rintf(x * inv0), -127.f), 127.f);
            float r  = x - d0 * d0s;
            float d1 = fminf(fmaxf(rintf(r * inv0 * 256.f), -127.f), 127.f);
            b0[i * 4 + j] = (signed char)(int)d0;
            b1[i * 4 + j] = (signed char)(int)d1;
        }
    }
    *(int4*)(q0 + (size_t)row * DFEAT + lane * 16) = *(int4*)b0;
    *(int4*)(q1 + (size_t)row * DFEAT + lane * 16) = *(int4*)b1;
}

__global__ void quant_X(const float* __restrict__ src) {
    const int row = blockIdx.x * (blockDim.x >> 5) + (threadIdx.x >> 5);
    quant_row_core(src, g_Xq0, g_Xq1, g_sX, row, threadIdx.x & 31);
}
__global__ void quant_D(const float* __restrict__ src) {
    const int row = blockIdx.x * (blockDim.x >> 5) + (threadIdx.x >> 5);
    quant_row_core(src, g_Dq0, g_Dq1, g_sD, row, threadIdx.x & 31);
}

// =======================  GEMM2: bf16 path (round-9)  ======================

__device__ __forceinline__ void load_tile(unsigned sbuf, const __nv_bfloat16* src,
                                          int rowBase, int K, int kOff, int tid) {
    const int row = tid >> 1;
    const int ch0 = (tid & 1) * 2;
    const char* g = (const char*)(src + (size_t)(rowBase + row) * K + kOff) + ch0 * 16;
    const int sw = (row >> 1) & 3;
    const unsigned s0 = sbuf + row * 64 + (((ch0)     ^ sw) << 4);
    const unsigned s1 = sbuf + row * 64 + (((ch0 + 1) ^ sw) << 4);
    asm volatile("cp.async.cg.shared.global [%0], [%1], 16;\n\t"
                 "cp.async.cg.shared.global [%2], [%3], 16;"
                 :: "r"(s0), "l"(g), "r"(s1), "l"(g + 16));
}

__device__ __forceinline__ void mma16(float* c, const unsigned* a, unsigned b0, unsigned b1) {
    asm volatile(
        "mma.sync.aligned.m16n8k16.row.col.f32.bf16.bf16.f32 "
        "{%0,%1,%2,%3}, {%4,%5,%6,%7}, {%8,%9}, {%0,%1,%2,%3};"
        : "+f"(c[0]), "+f"(c[1]), "+f"(c[2]), "+f"(c[3])
        : "r"(a[0]), "r"(a[1]), "r"(a[2]), "r"(a[3]), "r"(b0), "r"(b1));
}

__device__ __forceinline__ void compute3_k32(unsigned sAh, unsigned sAl,
                                             unsigned sBh, unsigned sBl,
                                             int warpM, int warpN, int lane,
                                             float (*c)[8][4]) {
#pragma unroll
    for (int kk = 0; kk < 32; kk += 16) {
        unsigned ah[2][4], al[2][4];
#pragma unroll
        for (int mi = 0; mi < 2; mi++) {
            const int r  = warpM * 32 + mi * 16 + (lane & 15);
            const int ch = (kk >> 3) + ((lane >> 4) & 1);
            const unsigned off = sw_addr(r, ch);
            LDSM4(ah[mi], sAh + off);
            LDSM4(al[mi], sAl + off);
        }
#pragma unroll
        for (int g = 0; g < 4; g++) {
            const int rb  = warpN * 64 + g * 16 + (lane & 7) + ((lane >> 4) & 1) * 8;
            const int chb = (kk >> 3) + ((lane >> 3) & 1);
            const unsigned boff = sw_addr(rb, chb);
            unsigned bh[4], bl[4];
            LDSM4(bh, sBh + boff);
            LDSM4(bl, sBl + boff);
            mma16(c[0][2 * g],     ah[0], bh[0], bh[1]);
            mma16(c[0][2 * g + 1], ah[0], bh[2], bh[3]);
            mma16(c[1][2 * g],     ah[1], bh[0], bh[1]);
            mma16(c[1][2 * g + 1], ah[1], bh[2], bh[3]);
            mma16(c[0][2 * g],     ah[0], bl[0], bl[1]);
            mma16(c[0][2 * g + 1], ah[0], bl[2], bl[3]);
            mma16(c[1][2 * g],     ah[1], bl[0], bl[1]);
            mma16(c[1][2 * g + 1], ah[1], bl[2], bl[3]);
            mma16(c[0][2 * g],     al[0], bh[0], bh[1]);
            mma16(c[0][2 * g + 1], al[0], bh[2], bh[3]);
            mma16(c[1][2 * g],     al[1], bh[0], bh[1]);
            mma16(c[1][2 * g + 1], al[1], bh[2], bh[3]);
        }
    }
}

__global__ __launch_bounds__(256, 2) void gemm2_mma(void) {
    extern __shared__ char dynsm[];
    const int tid = threadIdx.x, lane = tid & 31, wid = tid >> 5;
    const int warpM = wid & 3, warpN = wid >> 2;
    const int pBase = blockIdx.y * 128, jBase = blockIdx.x * 128;
    const int kBase = blockIdx.z * (NREF / 2);
    float* P = g_P + (size_t)blockIdx.z * PDIM * NIN;

    float c[2][8][4];
#pragma unroll
    for (int i = 0; i < 2; i++)
#pragma unroll
        for (int j = 0; j < 8; j++)
#pragma unroll
            for (int k = 0; k < 4; k++) c[i][j][k] = 0.0f;

    unsigned st[NSTAGE][4];
#pragma unroll
    for (int s = 0; s < NSTAGE; s++)
#pragma unroll
        for (int t = 0; t < 4; t++)
            st[s][t] = sm32(dynsm + s * STAGE_B + t * TILE_B);

#pragma unroll
    for (int s = 0; s < 2; s++) {
        const int kOff = kBase + s * 32;
        load_tile(st[s][0], g_Ah, pBase, NREF, kOff, tid);
        load_tile(st[s][1], g_Al, pBase, NREF, kOff, tid);
        load_tile(st[s][2], g_Kth, jBase, NREF, kOff, tid);
        load_tile(st[s][3], g_Ktl, jBase, NREF, kOff, tid);
        asm volatile("cp.async.commit_group;" ::: "memory");
    }

    const int NITER = (NREF / 2) / 32;  // 64
    for (int it = 0; it < NITER; it++) {
        asm volatile("cp.async.wait_group 1;" ::: "memory");
        __syncthreads();
        if (it + 2 < NITER) {
            const int s = (it + 2) % NSTAGE, kOff = kBase + (it + 2) * 32;
            load_tile(st[s][0], g_Ah, pBase, NREF, kOff, tid);
            load_tile(st[s][1], g_Al, pBase, NREF, kOff, tid);
            load_tile(st[s][2], g_Kth, jBase, NREF, kOff, tid);
            load_tile(st[s][3], g_Ktl, jBase, NREF, kOff, tid);
        }
        asm volatile("cp.async.commit_group;" ::: "memory");
        const int b = it % NSTAGE;
        compute3_k32(st[b][0], st[b][1], st[b][2], st[b][3], warpM, warpN, lane, c);
    }

#pragma unroll
    for (int mi = 0; mi < 2; mi++) {
        const int r0 = pBase + warpM * 32 + mi * 16 + (lane >> 2);
        const size_t ro0 = (size_t)r0 * NIN, ro1 = (size_t)(r0 + 8) * NIN;
#pragma unroll
        for (int ni = 0; ni < 8; ni++) {
            const int col = jBase + warpN * 64 + ni * 8 + 2 * (lane & 3);
            *(float2*)(P + ro0 + col) = make_float2(c[mi][ni][0], c[mi][ni][1]);
            *(float2*)(P + ro1 + col) = make_float2(c[mi][ni][2], c[mi][ni][3]);
        }
    }
}

__global__ void reduceY(float* __restrict__ Y) {
    int i = blockIdx.x * blockDim.x + threadIdx.x;
    const int n4 = PDIM * NIN / 4;
    if (i < n4) {
        float4 a = ((const float4*)g_P)[i];
        float4 b = ((const float4*)(g_P + PDIM * NIN))[i];
        ((float4*)Y)[i] = make_float4(a.x + b.x, a.y + b.y, a.z + b.z, a.w + b.w);
    }
}

__global__ void split_A(const float* __restrict__ x) {
    int i = blockIdx.x * blockDim.x + threadIdx.x;
    if (i < PDIM * NREF / 2) {
        float2 v = ((const float2*)x)[i];
        __nv_bfloat16 h0 = __float2bfloat16(v.x), h1 = __float2bfloat16(v.y);
        __nv_bfloat162 hh, ll;
        hh.x = h0; hh.y = h1;
        ll.x = __float2bfloat16(v.x - __bfloat162float(h0));
        ll.y = __float2bfloat16(v.y - __bfloat162float(h1));
        ((__nv_bfloat162*)g_Ah)[i] = hh;
        ((__nv_bfloat162*)g_Al)[i] = ll;
    }
}

extern "C" void kernel_launch(void* const* d_in, const int* in_sizes, int n_in,
                              void* d_out, int out_size) {
    const float* Alpha = (const float*)d_in[0];
    const float* X_ref = (const float*)d_in[1];
    const float* desc  = (const float*)d_in[2];
    const int*   Z_ref = (const int*)d_in[3];
    const int*   Z     = (const int*)d_in[4];
    const int*   expK  = (const int*)d_in[5];
    float* Y = (float*)d_out;

    cudaFuncSetAttribute(gemm1_imma, cudaFuncAttributeMaxDynamicSharedMemorySize, G1_SMEM);
    cudaFuncSetAttribute(gemm2_mma,  cudaFuncAttributeMaxDynamicSharedMemorySize, SMEM_TOTAL);

    quant_X<<<NREF / 8, 256>>>(X_ref);
    quant_D<<<NIN / 8, 256>>>(desc);
    split_A<<<(PDIM * NREF / 2 + 255) / 256, 256>>>(Alpha);

    gemm1_imma<<<dim3(NREF / 128, NIN / 128), 512, G1_SMEM>>>(Z, Z_ref, expK);
    gemm2_mma<<<dim3(NIN / 128, PDIM / 128, 2), 256, SMEM_TOTAL>>>();
    reduceY<<<(PDIM * NIN / 4 + 255) / 256, 256>>>(Y);
}

// round 13
// speedup vs baseline: 2.2003x; 2.2003x over previous
#include <cuda_runtime.h>
#include <cuda_bf16.h>
#include <cuda_fp16.h>

#define NREF  4096
#define NIN   8192
#define DFEAT 512
#define PDIM  256

// Swizzled tile: 128 rows x 32 halfwords = 64B/row.
#define TILE_B   8192                       // 128*64
#define STAGE_B  (4 * TILE_B)               // GEMM1: Dh, Dl, Xh, Xl
#define NSTAGE   3
#define SMEM_TOTAL (NSTAGE * STAGE_B + 512)

// GEMM2: 3 tiles per stage (A16, Kh, Kl)
#define G2_STAGE (3 * TILE_B)               // 24576
#define G2_SMEM  (NSTAGE * G2_STAGE + 512)

// ---------------- scratch (device globals) ----------------
__device__ __nv_bfloat16 g_Xh[NREF * DFEAT];
__device__ __nv_bfloat16 g_Xl[NREF * DFEAT];
__device__ __nv_bfloat16 g_Dh[NIN * DFEAT];
__device__ __nv_bfloat16 g_Dl[NIN * DFEAT];
__device__ __half g_A16[PDIM * NREF];
__device__ __half g_Kth[(size_t)NIN * NREF];   // K^T hi (fp16)
__device__ __half g_Ktl[(size_t)NIN * NREF];   // K^T lo (fp16)
__device__ float g_P[2 * PDIM * NIN];          // split-K partials

__device__ __forceinline__ unsigned sm32(const void* p) {
    unsigned r;
    asm("{.reg .u64 t; cvta.to.shared.u64 t, %1; cvt.u32.u64 %0, t;}" : "=r"(r) : "l"(p));
    return r;
}

// Load one 128x32 16-bit tile into swizzled smem. 256 threads, 2x16B each.
__device__ __forceinline__ void load_tile(unsigned sbuf, const void* src_,
                                          int rowBase, int K, int kOff, int tid) {
    const char* src = (const char*)src_;
    const int row = tid >> 1;
    const int ch0 = (tid & 1) * 2;
    const char* g = src + ((size_t)(rowBase + row) * K + kOff) * 2 + ch0 * 16;
    const int sw = (row >> 1) & 3;
    const unsigned s0 = sbuf + row * 64 + (((ch0)     ^ sw) << 4);
    const unsigned s1 = sbuf + row * 64 + (((ch0 + 1) ^ sw) << 4);
    asm volatile("cp.async.cg.shared.global [%0], [%1], 16;\n\t"
                 "cp.async.cg.shared.global [%2], [%3], 16;"
                 :: "r"(s0), "l"(g), "r"(s1), "l"(g + 16));
}

__device__ __forceinline__ void mma16bf(float* c, const unsigned* a, unsigned b0, unsigned b1) {
    asm volatile(
        "mma.sync.aligned.m16n8k16.row.col.f32.bf16.bf16.f32 "
        "{%0,%1,%2,%3}, {%4,%5,%6,%7}, {%8,%9}, {%0,%1,%2,%3};"
        : "+f"(c[0]), "+f"(c[1]), "+f"(c[2]), "+f"(c[3])
        : "r"(a[0]), "r"(a[1]), "r"(a[2]), "r"(a[3]), "r"(b0), "r"(b1));
}

__device__ __forceinline__ void mma16h(float* c, const unsigned* a, unsigned b0, unsigned b1) {
    asm volatile(
        "mma.sync.aligned.m16n8k16.row.col.f32.f16.f16.f32 "
        "{%0,%1,%2,%3}, {%4,%5,%6,%7}, {%8,%9}, {%0,%1,%2,%3};"
        : "+f"(c[0]), "+f"(c[1]), "+f"(c[2]), "+f"(c[3])
        : "r"(a[0]), "r"(a[1]), "r"(a[2]), "r"(a[3]), "r"(b0), "r"(b1));
}

#define LDSM4(r, addr)                                                           \
    asm volatile("ldmatrix.sync.aligned.m8n8.x4.shared.b16 {%0,%1,%2,%3}, [%4];" \
                 : "=r"((r)[0]), "=r"((r)[1]), "=r"((r)[2]), "=r"((r)[3])        \
                 : "r"(addr))

__device__ __forceinline__ unsigned sw_addr(int row, int ch) {
    return row * 64 + ((ch ^ ((row >> 1) & 3)) << 4);
}

// ================= GEMM1 compute: 3-term bf16 (round-9, proven) ============
__device__ __forceinline__ void compute3_k32(unsigned sAh, unsigned sAl,
                                             unsigned sBh, unsigned sBl,
                                             int warpM, int warpN, int lane,
                                             float (*c)[8][4]) {
#pragma unroll
    for (int kk = 0; kk < 32; kk += 16) {
        unsigned ah[2][4], al[2][4];
#pragma unroll
        for (int mi = 0; mi < 2; mi++) {
            const int r  = warpM * 32 + mi * 16 + (lane & 15);
            const int ch = (kk >> 3) + ((lane >> 4) & 1);
            const unsigned off = sw_addr(r, ch);
            LDSM4(ah[mi], sAh + off);
            LDSM4(al[mi], sAl + off);
        }
#pragma unroll
        for (int g = 0; g < 4; g++) {
            const int rb  = warpN * 64 + g * 16 + (lane & 7) + ((lane >> 4) & 1) * 8;
            const int chb = (kk >> 3) + ((lane >> 3) & 1);
            const unsigned boff = sw_addr(rb, chb);
            unsigned bh[4], bl[4];
            LDSM4(bh, sBh + boff);
            LDSM4(bl, sBl + boff);
            mma16bf(c[0][2 * g],     ah[0], bh[0], bh[1]);
            mma16bf(c[0][2 * g + 1], ah[0], bh[2], bh[3]);
            mma16bf(c[1][2 * g],     ah[1], bh[0], bh[1]);
            mma16bf(c[1][2 * g + 1], ah[1], bh[2], bh[3]);
            mma16bf(c[0][2 * g],     ah[0], bl[0], bl[1]);
            mma16bf(c[0][2 * g + 1], ah[0], bl[2], bl[3]);
            mma16bf(c[1][2 * g],     ah[1], bl[0], bl[1]);
            mma16bf(c[1][2 * g + 1], ah[1], bl[2], bl[3]);
            mma16bf(c[0][2 * g],     al[0], bh[0], bh[1]);
            mma16bf(c[0][2 * g + 1], al[0], bh[2], bh[3]);
            mma16bf(c[1][2 * g],     al[1], bh[0], bh[1]);
            mma16bf(c[1][2 * g + 1], al[1], bh[2], bh[3]);
        }
    }
}

// ---------------------------------------------------------------------------
// GEMM1 (transposed): Kt[j,i] = mask(Z[j]==Z_ref[i]) * (desc[j].X_ref[i])^expK
// Epilogue now emits fp16 hi/lo (for the fp16 GEMM2).
// ---------------------------------------------------------------------------
__global__ __launch_bounds__(256, 2) void gemm1_mma(const int* __restrict__ Zq,
                                                    const int* __restrict__ Zx,
                                                    const int* __restrict__ expKp) {
    extern __shared__ char dynsm[];
    const int tid = threadIdx.x, lane = tid & 31, wid = tid >> 5;
    const int warpM = wid & 3, warpN = wid >> 2;
    const int jBase = blockIdx.y * 128, iBase = blockIdx.x * 128;

    int* Zcol = (int*)(dynsm + NSTAGE * STAGE_B);
    if (tid < 128) Zcol[tid] = Zx[iBase + tid];

    float c[2][8][4];
#pragma unroll
    for (int i = 0; i < 2; i++)
#pragma unroll
        for (int j = 0; j < 8; j++)
#pragma unroll
            for (int k = 0; k < 4; k++) c[i][j][k] = 0.0f;

    unsigned st[NSTAGE][4];
#pragma unroll
    for (int s = 0; s < NSTAGE; s++)
#pragma unroll
        for (int t = 0; t < 4; t++)
            st[s][t] = sm32(dynsm + s * STAGE_B + t * TILE_B);

#pragma unroll
    for (int s = 0; s < 2; s++) {
        load_tile(st[s][0], g_Dh, jBase, DFEAT, s * 32, tid);
        load_tile(st[s][1], g_Dl, jBase, DFEAT, s * 32, tid);
        load_tile(st[s][2], g_Xh, iBase, DFEAT, s * 32, tid);
        load_tile(st[s][3], g_Xl, iBase, DFEAT, s * 32, tid);
        asm volatile("cp.async.commit_group;" ::: "memory");
    }

    const int NITER = DFEAT / 32;       // 16
    for (int it = 0; it < NITER; it++) {
        asm volatile("cp.async.wait_group 1;" ::: "memory");
        __syncthreads();
        if (it + 2 < NITER) {
            const int s = (it + 2) % NSTAGE, kOff = (it + 2) * 32;
            load_tile(st[s][0], g_Dh, jBase, DFEAT, kOff, tid);
            load_tile(st[s][1], g_Dl, jBase, DFEAT, kOff, tid);
            load_tile(st[s][2], g_Xh, iBase, DFEAT, kOff, tid);
            load_tile(st[s][3], g_Xl, iBase, DFEAT, kOff, tid);
        }
        asm volatile("cp.async.commit_group;" ::: "memory");
        const int b = it % NSTAGE;
        compute3_k32(st[b][0], st[b][1], st[b][2], st[b][3], warpM, warpN, lane, c);
    }

    // epilogue: pow, mask, fp16 hi/lo split, store K^T
    const int e = expKp[0];
#pragma unroll
    for (int mi = 0; mi < 2; mi++) {
        const int r0 = jBase + warpM * 32 + mi * 16 + (lane >> 2);
        const int zr0 = Zq[r0], zr1 = Zq[r0 + 8];
        const size_t ro0 = (size_t)r0 * NREF, ro1 = (size_t)(r0 + 8) * NREF;
#pragma unroll
        for (int ni = 0; ni < 8; ni++) {
            const int colL = warpN * 64 + ni * 8 + 2 * (lane & 3);
            const int zc0 = Zcol[colL], zc1 = Zcol[colL + 1];
            float v0 = c[mi][ni][0], v1 = c[mi][ni][1];
            float v2 = c[mi][ni][2], v3 = c[mi][ni][3];
            float p0 = 1.f, p1 = 1.f, p2 = 1.f, p3 = 1.f;
            for (int t = 0; t < e; t++) { p0 *= v0; p1 *= v1; p2 *= v2; p3 *= v3; }
            if (zr0 != zc0) p0 = 0.f;
            if (zr0 != zc1) p1 = 0.f;
            if (zr1 != zc0) p2 = 0.f;
            if (zr1 != zc1) p3 = 0.f;

            __half h0 = __float2half(p0), h1 = __float2half(p1);
            __half h2 = __float2half(p2), h3 = __float2half(p3);
            __half2 hh01 = __halves2half2(h0, h1);
            __half2 hh23 = __halves2half2(h2, h3);
            __half2 ll01 = __halves2half2(__float2half(p0 - __half2float(h0)),
                                          __float2half(p1 - __half2float(h1)));
            __half2 ll23 = __halves2half2(__float2half(p2 - __half2float(h2)),
                                          __float2half(p3 - __half2float(h3)));

            const size_t cg = (size_t)iBase + colL;
            *(__half2*)(g_Kth + ro0 + cg) = hh01;
            *(__half2*)(g_Kth + ro1 + cg) = hh23;
            *(__half2*)(g_Ktl + ro0 + cg) = ll01;
            *(__half2*)(g_Ktl + ro1 + cg) = ll23;
        }
    }
}

// ---------------------------------------------------------------------------
// GEMM2 (fp16, 2 terms): P[z][p,j] = A16[p, zK..] . (Kh + Kl)[j, zK..]
// grid (64, 2, 2) = 256 CTAs, 3-stage pipeline, one barrier per iteration.
// ---------------------------------------------------------------------------
__global__ __launch_bounds__(256, 2) void gemm2_mma(void) {
    extern __shared__ char dynsm[];
    const int tid = threadIdx.x, lane = tid & 31, wid = tid >> 5;
    const int warpM = wid & 3, warpN = wid >> 2;
    const int pBase = blockIdx.y * 128, jBase = blockIdx.x * 128;
    const int kBase = blockIdx.z * (NREF / 2);
    float* P = g_P + (size_t)blockIdx.z * PDIM * NIN;

    float c[2][8][4];
#pragma unroll
    for (int i = 0; i < 2; i++)
#pragma unroll
        for (int j = 0; j < 8; j++)
#pragma unroll
            for (int k = 0; k < 4; k++) c[i][j][k] = 0.0f;

    unsigned st[NSTAGE][3];
#pragma unroll
    for (int s = 0; s < NSTAGE; s++)
#pragma unroll
        for (int t = 0; t < 3; t++)
            st[s][t] = sm32(dynsm + s * G2_STAGE + t * TILE_B);

#pragma unroll
    for (int s = 0; s < 2; s++) {
        const int kOff = kBase + s * 32;
        load_tile(st[s][0], g_A16, pBase, NREF, kOff, tid);
        load_tile(st[s][1], g_Kth, jBase, NREF, kOff, tid);
        load_tile(st[s][2], g_Ktl, jBase, NREF, kOff, tid);
        asm volatile("cp.async.commit_group;" ::: "memory");
    }

    const int NITER = (NREF / 2) / 32;  // 64
    for (int it = 0; it < NITER; it++) {
        asm volatile("cp.async.wait_group 1;" ::: "memory");
        __syncthreads();
        if (it + 2 < NITER) {
            const int s = (it + 2) % NSTAGE, kOff = kBase + (it + 2) * 32;
            load_tile(st[s][0], g_A16, pBase, NREF, kOff, tid);
            load_tile(st[s][1], g_Kth, jBase, NREF, kOff, tid);
            load_tile(st[s][2], g_Ktl, jBase, NREF, kOff, tid);
        }
        asm volatile("cp.async.commit_group;" ::: "memory");
        const int b = it % NSTAGE;

        // compute: 32x64 warp tile, 2-term fp16
#pragma unroll
        for (int kk = 0; kk < 32; kk += 16) {
            unsigned a[2][4];
#pragma unroll
            for (int mi = 0; mi < 2; mi++) {
                const int r  = warpM * 32 + mi * 16 + (lane & 15);
                const int ch = (kk >> 3) + ((lane >> 4) & 1);
                LDSM4(a[mi], st[b][0] + sw_addr(r, ch));
            }
#pragma unroll
            for (int g = 0; g < 4; g++) {
                const int rb  = warpN * 64 + g * 16 + (lane & 7) + ((lane >> 4) & 1) * 8;
                const int chb = (kk >> 3) + ((lane >> 3) & 1);
                const unsigned boff = sw_addr(rb, chb);
                unsigned bh[4], bl[4];
                LDSM4(bh, st[b][1] + boff);
                LDSM4(bl, st[b][2] + boff);
                mma16h(c[0][2 * g],     a[0], bh[0], bh[1]);
                mma16h(c[0][2 * g + 1], a[0], bh[2], bh[3]);
                mma16h(c[1][2 * g],     a[1], bh[0], bh[1]);
                mma16h(c[1][2 * g + 1], a[1], bh[2], bh[3]);
                mma16h(c[0][2 * g],     a[0], bl[0], bl[1]);
                mma16h(c[0][2 * g + 1], a[0], bl[2], bl[3]);
                mma16h(c[1][2 * g],     a[1], bl[0], bl[1]);
                mma16h(c[1][2 * g + 1], a[1], bl[2], bl[3]);
            }
        }
    }

#pragma unroll
    for (int mi = 0; mi < 2; mi++) {
        const int r0 = pBase + warpM * 32 + mi * 16 + (lane >> 2);
        const size_t ro0 = (size_t)r0 * NIN, ro1 = (size_t)(r0 + 8) * NIN;
#pragma unroll
        for (int ni = 0; ni < 8; ni++) {
            const int col = jBase + warpN * 64 + ni * 8 + 2 * (lane & 3);
            *(float2*)(P + ro0 + col) = make_float2(c[mi][ni][0], c[mi][ni][1]);
            *(float2*)(P + ro1 + col) = make_float2(c[mi][ni][2], c[mi][ni][3]);
        }
    }
}

// Reduce the two split-K partials into the output.
__global__ void reduceY(float* __restrict__ Y) {
    int i = blockIdx.x * blockDim.x + threadIdx.x;
    const int n4 = PDIM * NIN / 4;
    if (i < n4) {
        float4 a = ((const float4*)g_P)[i];
        float4 b = ((const float4*)(g_P + PDIM * NIN))[i];
        ((float4*)Y)[i] = make_float4(a.x + b.x, a.y + b.y, a.z + b.z, a.w + b.w);
    }
}

// ---------------------------------------------------------------------------
// preprocessing kernels (device globals referenced only from device code)
// ---------------------------------------------------------------------------
__device__ __forceinline__ void split2(float2 v, __nv_bfloat162* hp, __nv_bfloat162* lp, int i) {
    __nv_bfloat16 h0 = __float2bfloat16(v.x), h1 = __float2bfloat16(v.y);
    __nv_bfloat162 hh, ll;
    hh.x = h0; hh.y = h1;
    ll.x = __float2bfloat16(v.x - __bfloat162float(h0));
    ll.y = __float2bfloat16(v.y - __bfloat162float(h1));
    hp[i] = hh; lp[i] = ll;
}
__global__ void split_X(const float* __restrict__ x) {
    int i = blockIdx.x * blockDim.x + threadIdx.x;
    if (i < NREF * DFEAT / 2)
        split2(((const float2*)x)[i], (__nv_bfloat162*)g_Xh, (__nv_bfloat162*)g_Xl, i);
}
__global__ void split_D(const float* __restrict__ x) {
    int i = blockIdx.x * blockDim.x + threadIdx.x;
    if (i < NIN * DFEAT / 2)
        split2(((const float2*)x)[i], (__nv_bfloat162*)g_Dh, (__nv_bfloat162*)g_Dl, i);
}
__global__ void conv_A16(const float* __restrict__ x) {
    int i = blockIdx.x * blockDim.x + threadIdx.x;
    if (i < PDIM * NREF / 2) {
        float2 v = ((const float2*)x)[i];
        ((__half2*)g_A16)[i] = __halves2half2(__float2half(v.x), __float2half(v.y));
    }
}

extern "C" void kernel_launch(void* const* d_in, const int* in_sizes, int n_in,
                              void* d_out, int out_size) {
    const float* Alpha = (const float*)d_in[0];
    const float* X_ref = (const float*)d_in[1];
    const float* desc  = (const float*)d_in[2];
    const int*   Z_ref = (const int*)d_in[3];
    const int*   Z     = (const int*)d_in[4];
    const int*   expK  = (const int*)d_in[5];
    float* Y = (float*)d_out;

    cudaFuncSetAttribute(gemm1_mma, cudaFuncAttributeMaxDynamicSharedMemorySize, SMEM_TOTAL);
    cudaFuncSetAttribute(gemm2_mma, cudaFuncAttributeMaxDynamicSharedMemorySize, G2_SMEM);

    split_X<<<(NREF * DFEAT / 2 + 255) / 256, 256>>>(X_ref);
    split_D<<<(NIN * DFEAT / 2 + 255) / 256, 256>>>(desc);
    conv_A16<<<(PDIM * NREF / 2 + 255) / 256, 256>>>(Alpha);

    gemm1_mma<<<dim3(NREF / 128, NIN / 128), 256, SMEM_TOTAL>>>(Z, Z_ref, expK);
    gemm2_mma<<<dim3(NIN / 128, PDIM / 128, 2), 256, G2_SMEM>>>();
    reduceY<<<(PDIM * NIN / 4 + 255) / 256, 256>>>(Y);
}

// round 14
// speedup vs baseline: 3.5475x; 1.6123x over previous
#include <cuda_runtime.h>
#include <cuda_bf16.h>
#include <cuda_fp16.h>

#define NREF  4096
#define NIN   8192
#define DFEAT 512
#define PDIM  256

// Swizzled tile: 128 rows x 32 halfwords = 64B/row.
#define TILE_B   8192                       // 128*64
#define NSTAGE   3

// GEMM1: 3 tiles per stage (Dh, Dl, X16)
#define G1_STAGE (3 * TILE_B)               // 24576
#define G1_SMEM  (NSTAGE * G1_STAGE + 512)
// GEMM2: 2 tiles per stage (A16, Kh)
#define G2_STAGE (2 * TILE_B)               // 16384
#define G2_SMEM  (NSTAGE * G2_STAGE + 512)

// ---------------- scratch (device globals) ----------------
__device__ __half g_X16[NREF * DFEAT];          // X_ref single fp16
__device__ __half g_Dh[NIN * DFEAT];            // desc fp16 hi
__device__ __half g_Dl[NIN * DFEAT];            // desc fp16 lo
__device__ __half g_A16[PDIM * NREF];           // Alpha single fp16
__device__ __half g_Kth[(size_t)NIN * NREF];    // K^T fp16
__device__ float g_P[2 * PDIM * NIN];           // split-K partials

__device__ __forceinline__ unsigned sm32(const void* p) {
    unsigned r;
    asm("{.reg .u64 t; cvta.to.shared.u64 t, %1; cvt.u32.u64 %0, t;}" : "=r"(r) : "l"(p));
    return r;
}

// Load one 128x32 16-bit tile into swizzled smem. 256 threads, 2x16B each.
__device__ __forceinline__ void load_tile(unsigned sbuf, const void* src_,
                                          int rowBase, int K, int kOff, int tid) {
    const char* src = (const char*)src_;
    const int row = tid >> 1;
    const int ch0 = (tid & 1) * 2;
    const char* g = src + ((size_t)(rowBase + row) * K + kOff) * 2 + ch0 * 16;
    const int sw = (row >> 1) & 3;
    const unsigned s0 = sbuf + row * 64 + (((ch0)     ^ sw) << 4);
    const unsigned s1 = sbuf + row * 64 + (((ch0 + 1) ^ sw) << 4);
    asm volatile("cp.async.cg.shared.global [%0], [%1], 16;\n\t"
                 "cp.async.cg.shared.global [%2], [%3], 16;"
                 :: "r"(s0), "l"(g), "r"(s1), "l"(g + 16));
}

__device__ __forceinline__ void mma16h(float* c, const unsigned* a, unsigned b0, unsigned b1) {
    asm volatile(
        "mma.sync.aligned.m16n8k16.row.col.f32.f16.f16.f32 "
        "{%0,%1,%2,%3}, {%4,%5,%6,%7}, {%8,%9}, {%0,%1,%2,%3};"
        : "+f"(c[0]), "+f"(c[1]), "+f"(c[2]), "+f"(c[3])
        : "r"(a[0]), "r"(a[1]), "r"(a[2]), "r"(a[3]), "r"(b0), "r"(b1));
}

#define LDSM4(r, addr)                                                           \
    asm volatile("ldmatrix.sync.aligned.m8n8.x4.shared.b16 {%0,%1,%2,%3}, [%4];" \
                 : "=r"((r)[0]), "=r"((r)[1]), "=r"((r)[2]), "=r"((r)[3])        \
                 : "r"(addr))

__device__ __forceinline__ unsigned sw_addr(int row, int ch) {
    return row * 64 + ((ch ^ ((row >> 1) & 3)) << 4);
}

// ---------------------------------------------------------------------------
// GEMM1 (transposed): Kt[j,i] = mask(Z[j]==Z_ref[i]) * ((Dh+Dl)[j].X16[i])^expK
// 2 MMA terms: Dh.X + Dl.X.  3-stage pipeline, 1 barrier/iter.
// ---------------------------------------------------------------------------
__global__ __launch_bounds__(256, 2) void gemm1_mma(const int* __restrict__ Zq,
                                                    const int* __restrict__ Zx,
                                                    const int* __restrict__ expKp) {
    extern __shared__ char dynsm[];
    const int tid = threadIdx.x, lane = tid & 31, wid = tid >> 5;
    const int warpM = wid & 3, warpN = wid >> 2;
    const int jBase = blockIdx.y * 128, iBase = blockIdx.x * 128;

    int* Zcol = (int*)(dynsm + NSTAGE * G1_STAGE);
    if (tid < 128) Zcol[tid] = Zx[iBase + tid];

    float c[2][8][4];
#pragma unroll
    for (int i = 0; i < 2; i++)
#pragma unroll
        for (int j = 0; j < 8; j++)
#pragma unroll
            for (int k = 0; k < 4; k++) c[i][j][k] = 0.0f;

    unsigned st[NSTAGE][3];
#pragma unroll
    for (int s = 0; s < NSTAGE; s++)
#pragma unroll
        for (int t = 0; t < 3; t++)
            st[s][t] = sm32(dynsm + s * G1_STAGE + t * TILE_B);

#pragma unroll
    for (int s = 0; s < 2; s++) {
        load_tile(st[s][0], g_Dh, jBase, DFEAT, s * 32, tid);
        load_tile(st[s][1], g_Dl, jBase, DFEAT, s * 32, tid);
        load_tile(st[s][2], g_X16, iBase, DFEAT, s * 32, tid);
        asm volatile("cp.async.commit_group;" ::: "memory");
    }

    const int NITER = DFEAT / 32;       // 16
    for (int it = 0; it < NITER; it++) {
        asm volatile("cp.async.wait_group 1;" ::: "memory");
        __syncthreads();
        if (it + 2 < NITER) {
            const int s = (it + 2) % NSTAGE, kOff = (it + 2) * 32;
            load_tile(st[s][0], g_Dh, jBase, DFEAT, kOff, tid);
            load_tile(st[s][1], g_Dl, jBase, DFEAT, kOff, tid);
            load_tile(st[s][2], g_X16, iBase, DFEAT, kOff, tid);
        }
        asm volatile("cp.async.commit_group;" ::: "memory");
        const int b = it % NSTAGE;

        // compute: 32x64 warp tile, 2 terms (Dh.X + Dl.X)
#pragma unroll
        for (int kk = 0; kk < 32; kk += 16) {
            unsigned dh[2][4], dl[2][4];
#pragma unroll
            for (int mi = 0; mi < 2; mi++) {
                const int r  = warpM * 32 + mi * 16 + (lane & 15);
                const int ch = (kk >> 3) + ((lane >> 4) & 1);
                const unsigned off = sw_addr(r, ch);
                LDSM4(dh[mi], st[b][0] + off);
                LDSM4(dl[mi], st[b][1] + off);
            }
#pragma unroll
            for (int g = 0; g < 4; g++) {
                const int rb  = warpN * 64 + g * 16 + (lane & 7) + ((lane >> 4) & 1) * 8;
                const int chb = (kk >> 3) + ((lane >> 3) & 1);
                unsigned bx[4];
                LDSM4(bx, st[b][2] + sw_addr(rb, chb));
                mma16h(c[0][2 * g],     dh[0], bx[0], bx[1]);
                mma16h(c[0][2 * g + 1], dh[0], bx[2], bx[3]);
                mma16h(c[1][2 * g],     dh[1], bx[0], bx[1]);
                mma16h(c[1][2 * g + 1], dh[1], bx[2], bx[3]);
                mma16h(c[0][2 * g],     dl[0], bx[0], bx[1]);
                mma16h(c[0][2 * g + 1], dl[0], bx[2], bx[3]);
                mma16h(c[1][2 * g],     dl[1], bx[0], bx[1]);
                mma16h(c[1][2 * g + 1], dl[1], bx[2], bx[3]);
            }
        }
    }

    // epilogue: pow, mask, fp16 store of K^T (single digit)
    const int e = expKp[0];
#pragma unroll
    for (int mi = 0; mi < 2; mi++) {
        const int r0 = jBase + warpM * 32 + mi * 16 + (lane >> 2);
        const int zr0 = Zq[r0], zr1 = Zq[r0 + 8];
        const size_t ro0 = (size_t)r0 * NREF, ro1 = (size_t)(r0 + 8) * NREF;
#pragma unroll
        for (int ni = 0; ni < 8; ni++) {
            const int colL = warpN * 64 + ni * 8 + 2 * (lane & 3);
            const int zc0 = Zcol[colL], zc1 = Zcol[colL + 1];
            float v0 = c[mi][ni][0], v1 = c[mi][ni][1];
            float v2 = c[mi][ni][2], v3 = c[mi][ni][3];
            float p0 = 1.f, p1 = 1.f, p2 = 1.f, p3 = 1.f;
            for (int t = 0; t < e; t++) { p0 *= v0; p1 *= v1; p2 *= v2; p3 *= v3; }
            if (zr0 != zc0) p0 = 0.f;
            if (zr0 != zc1) p1 = 0.f;
            if (zr1 != zc0) p2 = 0.f;
            if (zr1 != zc1) p3 = 0.f;

            const size_t cg = (size_t)iBase + colL;
            *(__half2*)(g_Kth + ro0 + cg) = __halves2half2(__float2half(p0), __float2half(p1));
            *(__half2*)(g_Kth + ro1 + cg) = __halves2half2(__float2half(p2), __float2half(p3));
        }
    }
}

// ---------------------------------------------------------------------------
// GEMM2 (fp16, 1 term): P[z][p,j] = A16[p, zK..] . Kh[j, zK..]
// grid (64, 2, 2) = 256 CTAs, 3-stage pipeline, one barrier per iteration.
// ---------------------------------------------------------------------------
__global__ __launch_bounds__(256, 2) void gemm2_mma(void) {
    extern __shared__ char dynsm[];
    const int tid = threadIdx.x, lane = tid & 31, wid = tid >> 5;
    const int warpM = wid & 3, warpN = wid >> 2;
    const int pBase = blockIdx.y * 128, jBase = blockIdx.x * 128;
    const int kBase = blockIdx.z * (NREF / 2);
    float* P = g_P + (size_t)blockIdx.z * PDIM * NIN;

    float c[2][8][4];
#pragma unroll
    for (int i = 0; i < 2; i++)
#pragma unroll
        for (int j = 0; j < 8; j++)
#pragma unroll
            for (int k = 0; k < 4; k++) c[i][j][k] = 0.0f;

    unsigned st[NSTAGE][2];
#pragma unroll
    for (int s = 0; s < NSTAGE; s++)
#pragma unroll
        for (int t = 0; t < 2; t++)
            st[s][t] = sm32(dynsm + s * G2_STAGE + t * TILE_B);

#pragma unroll
    for (int s = 0; s < 2; s++) {
        const int kOff = kBase + s * 32;
        load_tile(st[s][0], g_A16, pBase, NREF, kOff, tid);
        load_tile(st[s][1], g_Kth, jBase, NREF, kOff, tid);
        asm volatile("cp.async.commit_group;" ::: "memory");
    }

    const int NITER = (NREF / 2) / 32;  // 64
    for (int it = 0; it < NITER; it++) {
        asm volatile("cp.async.wait_group 1;" ::: "memory");
        __syncthreads();
        if (it + 2 < NITER) {
            const int s = (it + 2) % NSTAGE, kOff = kBase + (it + 2) * 32;
            load_tile(st[s][0], g_A16, pBase, NREF, kOff, tid);
            load_tile(st[s][1], g_Kth, jBase, NREF, kOff, tid);
        }
        asm volatile("cp.async.commit_group;" ::: "memory");
        const int b = it % NSTAGE;

        // compute: 32x64 warp tile, 1 term
#pragma unroll
        for (int kk = 0; kk < 32; kk += 16) {
            unsigned a[2][4];
#pragma unroll
            for (int mi = 0; mi < 2; mi++) {
                const int r  = warpM * 32 + mi * 16 + (lane & 15);
                const int ch = (kk >> 3) + ((lane >> 4) & 1);
                LDSM4(a[mi], st[b][0] + sw_addr(r, ch));
            }
#pragma unroll
            for (int g = 0; g < 4; g++) {
                const int rb  = warpN * 64 + g * 16 + (lane & 7) + ((lane >> 4) & 1) * 8;
                const int chb = (kk >> 3) + ((lane >> 3) & 1);
                unsigned bh[4];
                LDSM4(bh, st[b][1] + sw_addr(rb, chb));
                mma16h(c[0][2 * g],     a[0], bh[0], bh[1]);
                mma16h(c[0][2 * g + 1], a[0], bh[2], bh[3]);
                mma16h(c[1][2 * g],     a[1], bh[0], bh[1]);
                mma16h(c[1][2 * g + 1], a[1], bh[2], bh[3]);
            }
        }
    }

#pragma unroll
    for (int mi = 0; mi < 2; mi++) {
        const int r0 = pBase + warpM * 32 + mi * 16 + (lane >> 2);
        const size_t ro0 = (size_t)r0 * NIN, ro1 = (size_t)(r0 + 8) * NIN;
#pragma unroll
        for (int ni = 0; ni < 8; ni++) {
            const int col = jBase + warpN * 64 + ni * 8 + 2 * (lane & 3);
            *(float2*)(P + ro0 + col) = make_float2(c[mi][ni][0], c[mi][ni][1]);
            *(float2*)(P + ro1 + col) = make_float2(c[mi][ni][2], c[mi][ni][3]);
        }
    }
}

// Reduce the two split-K partials into the output.
__global__ void reduceY(float* __restrict__ Y) {
    int i = blockIdx.x * blockDim.x + threadIdx.x;
    const int n4 = PDIM * NIN / 4;
    if (i < n4) {
        float4 a = ((const float4*)g_P)[i];
        float4 b = ((const float4*)(g_P + PDIM * NIN))[i];
        ((float4*)Y)[i] = make_float4(a.x + b.x, a.y + b.y, a.z + b.z, a.w + b.w);
    }
}

// ---------------------------------------------------------------------------
// preprocessing kernels (device globals referenced only from device code)
// ---------------------------------------------------------------------------
__global__ void conv_X16(const float* __restrict__ x) {
    int i = blockIdx.x * blockDim.x + threadIdx.x;
    if (i < NREF * DFEAT / 2) {
        float2 v = ((const float2*)x)[i];
        ((__half2*)g_X16)[i] = __halves2half2(__float2half(v.x), __float2half(v.y));
    }
}
__global__ void split_D16(const float* __restrict__ x) {
    int i = blockIdx.x * blockDim.x + threadIdx.x;
    if (i < NIN * DFEAT / 2) {
        float2 v = ((const float2*)x)[i];
        __half h0 = __float2half(v.x), h1 = __float2half(v.y);
        ((__half2*)g_Dh)[i] = __halves2half2(h0, h1);
        ((__half2*)g_Dl)[i] = __halves2half2(__float2half(v.x - __half2float(h0)),
                                             __float2half(v.y - __half2float(h1)));
    }
}
__global__ void conv_A16(const float* __restrict__ x) {
    int i = blockIdx.x * blockDim.x + threadIdx.x;
    if (i < PDIM * NREF / 2) {
        float2 v = ((const float2*)x)[i];
        ((__half2*)g_A16)[i] = __halves2half2(__float2half(v.x), __float2half(v.y));
    }
}

extern "C" void kernel_launch(void* const* d_in, const int* in_sizes, int n_in,
                              void* d_out, int out_size) {
    const float* Alpha = (const float*)d_in[0];
    const float* X_ref = (const float*)d_in[1];
    const float* desc  = (const float*)d_in[2];
    const int*   Z_ref = (const int*)d_in[3];
    const int*   Z     = (const int*)d_in[4];
    const int*   expK  = (const int*)d_in[5];
    float* Y = (float*)d_out;

    cudaFuncSetAttribute(gemm1_mma, cudaFuncAttributeMaxDynamicSharedMemorySize, G1_SMEM);
    cudaFuncSetAttribute(gemm2_mma, cudaFuncAttributeMaxDynamicSharedMemorySize, G2_SMEM);

    conv_X16<<<(NREF * DFEAT / 2 + 255) / 256, 256>>>(X_ref);
    split_D16<<<(NIN * DFEAT / 2 + 255) / 256, 256>>>(desc);
    conv_A16<<<(PDIM * NREF / 2 + 255) / 256, 256>>>(Alpha);

    gemm1_mma<<<dim3(NREF / 128, NIN / 128), 256, G1_SMEM>>>(Z, Z_ref, expK);
    gemm2_mma<<<dim3(NIN / 128, PDIM / 128, 2), 256, G2_SMEM>>>();
    reduceY<<<(PDIM * NIN / 4 + 255) / 256, 256>>>(Y);
}

// round 15
// speedup vs baseline: 3.9665x; 1.1181x over previous
#include <cuda_runtime.h>
#include <cuda_fp16.h>

#define NREF  4096
#define NIN   8192
#define DFEAT 512
#define PDIM  256
#define NELEM 4

#define RTOTP 4608            // 4096 + 4*128 capacity, 128-aligned regions
#define QTOTP 8704            // 8192 + 4*128
#define MAXT1 2560
#define MAXT2 80

// Swizzled tile: 128 rows x 32 halfwords = 64B/row.
#define TILE_B   8192
#define NSTAGE   3
#define G1_STAGE (3 * TILE_B)               // Dh, Dl, X16
#define G1_SMEM  (NSTAGE * G1_STAGE + 512)
#define G2_STAGE (2 * TILE_B)               // A16, Kh
#define G2_SMEM  (NSTAGE * G2_STAGE + 512)

// ---------------- scratch (device globals; device-code refs only) ----------
__device__ __half g_X16g[RTOTP * DFEAT];
__device__ __half g_Dhg[(size_t)QTOTP * DFEAT];
__device__ __half g_Dlg[(size_t)QTOTP * DFEAT];
__device__ __half g_A16g[PDIM * RTOTP];
__device__ __half g_Ktp[(size_t)QTOTP * RTOTP];   // padded-permuted K^T
__device__ float  g_P[2 * PDIM * QTOTP];
__device__ int  g_rslot2orig[RTOTP];
__device__ int  g_qslot2orig[QTOTP];
__device__ int  g_qinv[NIN];
__device__ int  g_Roff[NELEM + 1];
__device__ int  g_nT1;
__device__ int2 g_T1[MAXT1];                      // (jBase, iBase)
__device__ int  g_nT2;
__device__ int2 g_T2[MAXT2];                      // (jBase, elem)

__device__ __forceinline__ unsigned sm32(const void* p) {
    unsigned r;
    asm("{.reg .u64 t; cvta.to.shared.u64 t, %1; cvt.u32.u64 %0, t;}" : "=r"(r) : "l"(p));
    return r;
}

// ---------------------------------------------------------------------------
// build_meta: deterministic counting sort by element + tile tables. 1 CTA.
// ---------------------------------------------------------------------------
__global__ void build_meta(const int* __restrict__ Zr, const int* __restrict__ Zq) {
    __shared__ uint4 scan[1024];
    __shared__ int cnt[NELEM], base[NELEM];
    __shared__ int roff[NELEM + 1], qoff[NELEM + 1];
    const int tid = threadIdx.x;

    // ---- ref histogram + offsets ----
    if (tid < NELEM) cnt[tid] = 0;
    __syncthreads();
    for (int i = tid; i < NREF; i += 1024) atomicAdd(&cnt[Zr[i]], 1);
    __syncthreads();
    if (tid == 0) {
        roff[0] = 0;
        for (int e = 0; e < NELEM; e++) roff[e + 1] = roff[e] + ((cnt[e] + 127) & ~127);
        for (int e = 0; e <= NELEM; e++) g_Roff[e] = roff[e];
    }
    __syncthreads();
    for (int i = tid; i < RTOTP; i += 1024) g_rslot2orig[i] = -1;
    if (tid < NELEM) base[tid] = 0;
    __syncthreads();
    // ---- ref slot assignment via chunked prefix scan ----
    for (int c = 0; c < NREF / 1024; c++) {
        const int z = Zr[c * 1024 + tid];
        scan[tid] = make_uint4(z == 0, z == 1, z == 2, z == 3);
        __syncthreads();
        for (int off = 1; off < 1024; off <<= 1) {
            uint4 add = make_uint4(0, 0, 0, 0);
            if (tid >= off) add = scan[tid - off];
            __syncthreads();
            uint4 cur = scan[tid];
            cur.x += add.x; cur.y += add.y; cur.z += add.z; cur.w += add.w;
            scan[tid] = cur;
            __syncthreads();
        }
        uint4 incl = scan[tid];
        const int rank = (int)(z == 0 ? incl.x : z == 1 ? incl.y : z == 2 ? incl.z : incl.w) - 1;
        g_rslot2orig[roff[z] + base[z] + rank] = c * 1024 + tid;
        __syncthreads();
        if (tid == 0) {
            uint4 tot = scan[1023];
            base[0] += tot.x; base[1] += tot.y; base[2] += tot.z; base[3] += tot.w;
        }
        __syncthreads();
    }

    // ---- query histogram + offsets ----
    if (tid < NELEM) cnt[tid] = 0;
    __syncthreads();
    for (int i = tid; i < NIN; i += 1024) atomicAdd(&cnt[Zq[i]], 1);
    __syncthreads();
    if (tid == 0) {
        qoff[0] = 0;
        for (int e = 0; e < NELEM; e++) qoff[e + 1] = qoff[e] + ((cnt[e] + 127) & ~127);
    }
    __syncthreads();
    for (int i = tid; i < QTOTP; i += 1024) g_qslot2orig[i] = -1;
    if (tid < NELEM) base[tid] = 0;
    __syncthreads();
    for (int c = 0; c < NIN / 1024; c++) {
        const int z = Zq[c * 1024 + tid];
        scan[tid] = make_uint4(z == 0, z == 1, z == 2, z == 3);
        __syncthreads();
        for (int off = 1; off < 1024; off <<= 1) {
            uint4 add = make_uint4(0, 0, 0, 0);
            if (tid >= off) add = scan[tid - off];
            __syncthreads();
            uint4 cur = scan[tid];
            cur.x += add.x; cur.y += add.y; cur.z += add.z; cur.w += add.w;
            scan[tid] = cur;
            __syncthreads();
        }
        uint4 incl = scan[tid];
        const int rank = (int)(z == 0 ? incl.x : z == 1 ? incl.y : z == 2 ? incl.z : incl.w) - 1;
        const int slot = qoff[z] + base[z] + rank;
        g_qslot2orig[slot] = c * 1024 + tid;
        g_qinv[c * 1024 + tid] = slot;
        __syncthreads();
        if (tid == 0) {
            uint4 tot = scan[1023];
            base[0] += tot.x; base[1] += tot.y; base[2] += tot.z; base[3] += tot.w;
        }
        __syncthreads();
    }

    // ---- tile tables ----
    if (tid == 0) {
        int n1 = 0;
        for (int e = 0; e < NELEM; e++) {
            const int qt = (qoff[e + 1] - qoff[e]) / 128;
            const int rt = (roff[e + 1] - roff[e]) / 128;
            for (int jt = 0; jt < qt; jt++)
                for (int it = 0; it < rt; it++)
                    g_T1[n1++] = make_int2(qoff[e] + jt * 128, roff[e] + it * 128);
        }
        g_nT1 = n1;
        int n2 = 0;
        for (int e = 0; e < NELEM; e++) {
            const int qt = (qoff[e + 1] - qoff[e]) / 128;
            for (int jt = 0; jt < qt; jt++)
                g_T2[n2++] = make_int2(qoff[e] + jt * 128, e);
        }
        g_nT2 = n2;
    }
}

// ---------------------------------------------------------------------------
// gather / convert kernels
// ---------------------------------------------------------------------------
__global__ void gather_X(const float* __restrict__ X) {
    const int row = blockIdx.x;                     // < RTOTP
    const int orig = g_rslot2orig[row];
    __half2* dst = (__half2*)(g_X16g + (size_t)row * DFEAT);
    if (orig < 0) {
        const __half2 z = __halves2half2(__float2half(0.f), __float2half(0.f));
        for (int c = threadIdx.x; c < DFEAT / 2; c += 256) dst[c] = z;
    } else {
        const float2* src = (const float2*)(X + (size_t)orig * DFEAT);
        for (int c = threadIdx.x; c < DFEAT / 2; c += 256) {
            float2 v = src[c];
            dst[c] = __halves2half2(__float2half(v.x), __float2half(v.y));
        }
    }
}

__global__ void gather_D(const float* __restrict__ D) {
    const int row = blockIdx.x;                     // < QTOTP
    const int orig = g_qslot2orig[row];
    __half2* dh = (__half2*)(g_Dhg + (size_t)row * DFEAT);
    __half2* dl = (__half2*)(g_Dlg + (size_t)row * DFEAT);
    if (orig < 0) {
        const __half2 z = __halves2half2(__float2half(0.f), __float2half(0.f));
        for (int c = threadIdx.x; c < DFEAT / 2; c += 256) { dh[c] = z; dl[c] = z; }
    } else {
        const float2* src = (const float2*)(D + (size_t)orig * DFEAT);
        for (int c = threadIdx.x; c < DFEAT / 2; c += 256) {
            float2 v = src[c];
            __half h0 = __float2half(v.x), h1 = __float2half(v.y);
            dh[c] = __halves2half2(h0, h1);
            dl[c] = __halves2half2(__float2half(v.x - __half2float(h0)),
                                   __float2half(v.y - __half2float(h1)));
        }
    }
}

__global__ void gather_A(const float* __restrict__ A) {
    const int i = blockIdx.x * blockDim.x + threadIdx.x;
    if (i < PDIM * RTOTP) {
        const int p = i / RTOTP, s = i - p * RTOTP;
        const int orig = g_rslot2orig[s];
        const float v = (orig < 0) ? 0.f : A[(size_t)p * NREF + orig];
        g_A16g[i] = __float2half(v);
    }
}

// ---------------------------------------------------------------------------
// shared GEMM machinery (round-14 proven)
// ---------------------------------------------------------------------------
__device__ __forceinline__ void load_tile(unsigned sbuf, const void* src_,
                                          int rowBase, int K, int kOff, int tid) {
    const char* src = (const char*)src_;
    const int row = tid >> 1;
    const int ch0 = (tid & 1) * 2;
    const char* g = src + ((size_t)(rowBase + row) * K + kOff) * 2 + ch0 * 16;
    const int sw = (row >> 1) & 3;
    const unsigned s0 = sbuf + row * 64 + (((ch0)     ^ sw) << 4);
    const unsigned s1 = sbuf + row * 64 + (((ch0 + 1) ^ sw) << 4);
    asm volatile("cp.async.cg.shared.global [%0], [%1], 16;\n\t"
                 "cp.async.cg.shared.global [%2], [%3], 16;"
                 :: "r"(s0), "l"(g), "r"(s1), "l"(g + 16));
}

__device__ __forceinline__ void mma16h(float* c, const unsigned* a, unsigned b0, unsigned b1) {
    asm volatile(
        "mma.sync.aligned.m16n8k16.row.col.f32.f16.f16.f32 "
        "{%0,%1,%2,%3}, {%4,%5,%6,%7}, {%8,%9}, {%0,%1,%2,%3};"
        : "+f"(c[0]), "+f"(c[1]), "+f"(c[2]), "+f"(c[3])
        : "r"(a[0]), "r"(a[1]), "r"(a[2]), "r"(a[3]), "r"(b0), "r"(b1));
}

#define LDSM4(r, addr)                                                           \
    asm volatile("ldmatrix.sync.aligned.m8n8.x4.shared.b16 {%0,%1,%2,%3}, [%4];" \
                 : "=r"((r)[0]), "=r"((r)[1]), "=r"((r)[2]), "=r"((r)[3])        \
                 : "r"(addr))

__device__ __forceinline__ unsigned sw_addr(int row, int ch) {
    return row * 64 + ((ch ^ ((row >> 1) & 3)) << 4);
}

// ---------------------------------------------------------------------------
// GEMM1 (grouped): Ktp[jslot, islot] = (desc_g[j] . X_g[i])^expK  (no mask!)
// ---------------------------------------------------------------------------
__global__ __launch_bounds__(256, 2) void gemm1_mma(const int* __restrict__ expKp) {
    if (blockIdx.x >= g_nT1) return;
    extern __shared__ char dynsm[];
    const int tid = threadIdx.x, lane = tid & 31, wid = tid >> 5;
    const int warpM = wid & 3, warpN = wid >> 2;
    const int2 t = g_T1[blockIdx.x];
    const int jBase = t.x, iBase = t.y;

    float c[2][8][4];
#pragma unroll
    for (int i = 0; i < 2; i++)
#pragma unroll
        for (int j = 0; j < 8; j++)
#pragma unroll
            for (int k = 0; k < 4; k++) c[i][j][k] = 0.0f;

    unsigned st[NSTAGE][3];
#pragma unroll
    for (int s = 0; s < NSTAGE; s++)
#pragma unroll
        for (int tt = 0; tt < 3; tt++)
            st[s][tt] = sm32(dynsm + s * G1_STAGE + tt * TILE_B);

#pragma unroll
    for (int s = 0; s < 2; s++) {
        load_tile(st[s][0], g_Dhg, jBase, DFEAT, s * 32, tid);
        load_tile(st[s][1], g_Dlg, jBase, DFEAT, s * 32, tid);
        load_tile(st[s][2], g_X16g, iBase, DFEAT, s * 32, tid);
        asm volatile("cp.async.commit_group;" ::: "memory");
    }

    const int NITER = DFEAT / 32;       // 16
    for (int it = 0; it < NITER; it++) {
        asm volatile("cp.async.wait_group 1;" ::: "memory");
        __syncthreads();
        if (it + 2 < NITER) {
            const int s = (it + 2) % NSTAGE, kOff = (it + 2) * 32;
            load_tile(st[s][0], g_Dhg, jBase, DFEAT, kOff, tid);
            load_tile(st[s][1], g_Dlg, jBase, DFEAT, kOff, tid);
            load_tile(st[s][2], g_X16g, iBase, DFEAT, kOff, tid);
        }
        asm volatile("cp.async.commit_group;" ::: "memory");
        const int b = it % NSTAGE;

#pragma unroll
        for (int kk = 0; kk < 32; kk += 16) {
            unsigned dh[2][4], dl[2][4];
#pragma unroll
            for (int mi = 0; mi < 2; mi++) {
                const int r  = warpM * 32 + mi * 16 + (lane & 15);
                const int ch = (kk >> 3) + ((lane >> 4) & 1);
                const unsigned off = sw_addr(r, ch);
                LDSM4(dh[mi], st[b][0] + off);
                LDSM4(dl[mi], st[b][1] + off);
            }
#pragma unroll
            for (int g = 0; g < 4; g++) {
                const int rb  = warpN * 64 + g * 16 + (lane & 7) + ((lane >> 4) & 1) * 8;
                const int chb = (kk >> 3) + ((lane >> 3) & 1);
                unsigned bx[4];
                LDSM4(bx, st[b][2] + sw_addr(rb, chb));
                mma16h(c[0][2 * g],     dh[0], bx[0], bx[1]);
                mma16h(c[0][2 * g + 1], dh[0], bx[2], bx[3]);
                mma16h(c[1][2 * g],     dh[1], bx[0], bx[1]);
                mma16h(c[1][2 * g + 1], dh[1], bx[2], bx[3]);
                mma16h(c[0][2 * g],     dl[0], bx[0], bx[1]);
                mma16h(c[0][2 * g + 1], dl[0], bx[2], bx[3]);
                mma16h(c[1][2 * g],     dl[1], bx[0], bx[1]);
                mma16h(c[1][2 * g + 1], dl[1], bx[2], bx[3]);
            }
        }
    }

    // epilogue: pow only (mask implicit), fp16 store to padded K^T
    const int e = expKp[0];
#pragma unroll
    for (int mi = 0; mi < 2; mi++) {
        const int r0 = jBase + warpM * 32 + mi * 16 + (lane >> 2);
        const size_t ro0 = (size_t)r0 * RTOTP, ro1 = (size_t)(r0 + 8) * RTOTP;
#pragma unroll
        for (int ni = 0; ni < 8; ni++) {
            const int colL = warpN * 64 + ni * 8 + 2 * (lane & 3);
            float v0 = c[mi][ni][0], v1 = c[mi][ni][1];
            float v2 = c[mi][ni][2], v3 = c[mi][ni][3];
            float p0 = 1.f, p1 = 1.f, p2 = 1.f, p3 = 1.f;
            for (int t2 = 0; t2 < e; t2++) { p0 *= v0; p1 *= v1; p2 *= v2; p3 *= v3; }
            const size_t cg = (size_t)iBase + colL;
            *(__half2*)(g_Ktp + ro0 + cg) = __halves2half2(__float2half(p0), __float2half(p1));
            *(__half2*)(g_Ktp + ro1 + cg) = __halves2half2(__float2half(p2), __float2half(p3));
        }
    }
}

// ---------------------------------------------------------------------------
// GEMM2 (grouped, 1-term fp16): P[z][p, jslot] = A16g[p, Ke..] . Ktp[jslot, Ke..]
// ---------------------------------------------------------------------------
__global__ __launch_bounds__(256, 2) void gemm2_mma(void) {
    if (blockIdx.x >= g_nT2) return;
    extern __shared__ char dynsm[];
    const int tid = threadIdx.x, lane = tid & 31, wid = tid >> 5;
    const int warpM = wid & 3, warpN = wid >> 2;
    const int2 t = g_T2[blockIdx.x];
    const int jBase = t.x, elem = t.y;
    const int pBase = blockIdx.y * 128;
    const int rbeg = g_Roff[elem];
    const int half = (g_Roff[elem + 1] - rbeg) >> 1;   // multiple of 64
    const int kBase = rbeg + blockIdx.z * half;
    const int NITER = half / 32;
    float* P = g_P + (size_t)blockIdx.z * PDIM * QTOTP;

    float c[2][8][4];
#pragma unroll
    for (int i = 0; i < 2; i++)
#pragma unroll
        for (int j = 0; j < 8; j++)
#pragma unroll
            for (int k = 0; k < 4; k++) c[i][j][k] = 0.0f;

    unsigned st[NSTAGE][2];
#pragma unroll
    for (int s = 0; s < NSTAGE; s++)
#pragma unroll
        for (int tt = 0; tt < 2; tt++)
            st[s][tt] = sm32(dynsm + s * G2_STAGE + tt * TILE_B);

#pragma unroll
    for (int s = 0; s < 2; s++) {
        if (s < NITER) {
            const int kOff = kBase + s * 32;
            load_tile(st[s][0], g_A16g, pBase, RTOTP, kOff, tid);
            load_tile(st[s][1], g_Ktp, jBase, RTOTP, kOff, tid);
        }
        asm volatile("cp.async.commit_group;" ::: "memory");
    }

    for (int it = 0; it < NITER; it++) {
        asm volatile("cp.async.wait_group 1;" ::: "memory");
        __syncthreads();
        if (it + 2 < NITER) {
            const int s = (it + 2) % NSTAGE, kOff = kBase + (it + 2) * 32;
            load_tile(st[s][0], g_A16g, pBase, RTOTP, kOff, tid);
            load_tile(st[s][1], g_Ktp, jBase, RTOTP, kOff, tid);
        }
        asm volatile("cp.async.commit_group;" ::: "memory");
        const int b = it % NSTAGE;

#pragma unroll
        for (int kk = 0; kk < 32; kk += 16) {
            unsigned a[2][4];
#pragma unroll
            for (int mi = 0; mi < 2; mi++) {
                const int r  = warpM * 32 + mi * 16 + (lane & 15);
                const int ch = (kk >> 3) + ((lane >> 4) & 1);
                LDSM4(a[mi], st[b][0] + sw_addr(r, ch));
            }
#pragma unroll
            for (int g = 0; g < 4; g++) {
                const int rb  = warpN * 64 + g * 16 + (lane & 7) + ((lane >> 4) & 1) * 8;
                const int chb = (kk >> 3) + ((lane >> 3) & 1);
                unsigned bh[4];
                LDSM4(bh, st[b][1] + sw_addr(rb, chb));
                mma16h(c[0][2 * g],     a[0], bh[0], bh[1]);
                mma16h(c[0][2 * g + 1], a[0], bh[2], bh[3]);
                mma16h(c[1][2 * g],     a[1], bh[0], bh[1]);
                mma16h(c[1][2 * g + 1], a[1], bh[2], bh[3]);
            }
        }
    }

    // NOTE: M side here is P rows (pBase..pBase+127), N side is jslot columns.
#pragma unroll
    for (int mi = 0; mi < 2; mi++) {
        const int r0 = pBase + warpM * 32 + mi * 16 + (lane >> 2);
        const size_t ro0 = (size_t)r0 * QTOTP, ro1 = (size_t)(r0 + 8) * QTOTP;
#pragma unroll
        for (int ni = 0; ni < 8; ni++) {
            const int col = jBase + warpN * 64 + ni * 8 + 2 * (lane & 3);
            *(float2*)(P + ro0 + col) = make_float2(c[mi][ni][0], c[mi][ni][1]);
            *(float2*)(P + ro1 + col) = make_float2(c[mi][ni][2], c[mi][ni][3]);
        }
    }
}

// Reduce split-K partials + unpermute columns into the output.
__global__ void reduceY(float* __restrict__ Y) {
    const int i = blockIdx.x * blockDim.x + threadIdx.x;
    if (i < PDIM * NIN) {
        const int p = i / NIN, j = i - p * NIN;
        const int s = g_qinv[j];
        const size_t off = (size_t)p * QTOTP + s;
        Y[i] = g_P[off] + g_P[(size_t)PDIM * QTOTP + off];
    }
}

extern "C" void kernel_launch(void* const* d_in, const int* in_sizes, int n_in,
                              void* d_out, int out_size) {
    const float* Alpha = (const float*)d_in[0];
    const float* X_ref = (const float*)d_in[1];
    const float* desc  = (const float*)d_in[2];
    const int*   Z_ref = (const int*)d_in[3];
    const int*   Z     = (const int*)d_in[4];
    const int*   expK  = (const int*)d_in[5];
    float* Y = (float*)d_out;

    cudaFuncSetAttribute(gemm1_mma, cudaFuncAttributeMaxDynamicSharedMemorySize, G1_SMEM);
    cudaFuncSetAttribute(gemm2_mma, cudaFuncAttributeMaxDynamicSharedMemorySize, G2_SMEM);

    build_meta<<<1, 1024>>>(Z_ref, Z);
    gather_X<<<RTOTP, 256>>>(X_ref);
    gather_D<<<QTOTP, 256>>>(desc);
    gather_A<<<(PDIM * RTOTP + 255) / 256, 256>>>(Alpha);

    gemm1_mma<<<MAXT1, 256, G1_SMEM>>>(expK);
    gemm2_mma<<<dim3(QTOTP / 128, PDIM / 128, 2), 256, G2_SMEM>>>();
    reduceY<<<(PDIM * NIN + 255) / 256, 256>>>(Y);
}

// round 16
// speedup vs baseline: 8.6992x; 2.1931x over previous
#include <cuda_runtime.h>
#include <cuda_fp16.h>

#define NREF  4096
#define NIN   8192
#define DFEAT 512
#define PDIM  256
#define NELEM 4

#define RTOTP 4608
#define QTOTP 8704
#define MAXT1 2560
#define NCH_R 4               // ref chunks of 1024
#define NCH_Q 8               // query chunks of 1024
#define NCH   (NCH_R + NCH_Q)

#define TILE_B   8192
#define NSTAGE   3
#define G1_STAGE (2 * TILE_B)               // D16, X16
#define G1_SMEM  (NSTAGE * G1_STAGE + 512)
#define G2_STAGE (2 * TILE_B)               // A16, Kh
#define G2_SMEM  (NSTAGE * G2_STAGE + 512)

// ---------------- scratch (device globals; device-code refs only) ----------
__device__ __half g_X16g[RTOTP * DFEAT];
__device__ __half g_D16g[(size_t)QTOTP * DFEAT];
__device__ __half g_A16g[PDIM * RTOTP];
__device__ __half g_Ktp[(size_t)QTOTP * RTOTP];
__device__ float  g_P[2 * PDIM * QTOTP];
__device__ int  g_rslot2orig[RTOTP];
__device__ int  g_qslot2orig[QTOTP];
__device__ int  g_qinv[NIN];
__device__ int  g_Roff[NELEM + 1];
__device__ int  g_Qoff[NELEM + 1];
__device__ int  g_chunkCnt[NCH][NELEM];
__device__ int  g_chunkBase[NCH][NELEM];
__device__ int  g_nT1;
__device__ int2 g_T1[MAXT1];
__device__ int  g_nT2;
__device__ int2 g_T2[80];

__device__ __forceinline__ unsigned sm32(const void* p) {
    unsigned r;
    asm("{.reg .u64 t; cvta.to.shared.u64 t, %1; cvt.u32.u64 %0, t;}" : "=r"(r) : "l"(p));
    return r;
}

// ---------------------------------------------------------------------------
// meta pass 1: per-chunk element histograms (12 CTAs in parallel)
// ---------------------------------------------------------------------------
__global__ void meta_hist(const int* __restrict__ Zr, const int* __restrict__ Zq) {
    __shared__ int cnt[NELEM];
    const int c = blockIdx.x, tid = threadIdx.x;
    if (tid < NELEM) cnt[tid] = 0;
    __syncthreads();
    const int z = (c < NCH_R) ? Zr[c * 1024 + tid] : Zq[(c - NCH_R) * 1024 + tid];
    atomicAdd(&cnt[z], 1);
    __syncthreads();
    if (tid < NELEM) g_chunkCnt[c][tid] = cnt[tid];
}

// ---------------------------------------------------------------------------
// meta pass 2: offsets, per-chunk bases, tile tables, init slot maps (1 CTA)
// ---------------------------------------------------------------------------
__global__ void meta_off(void) {
    const int tid = threadIdx.x;
    for (int i = tid; i < RTOTP; i += 1024) g_rslot2orig[i] = -1;
    for (int i = tid; i < QTOTP; i += 1024) g_qslot2orig[i] = -1;
    __syncthreads();
    if (tid == 0) {
        int roff[NELEM + 1], qoff[NELEM + 1];
        roff[0] = 0; qoff[0] = 0;
        for (int e = 0; e < NELEM; e++) {
            int rc = 0, qc = 0;
            for (int c = 0; c < NCH_R; c++) rc += g_chunkCnt[c][e];
            for (int c = NCH_R; c < NCH; c++) qc += g_chunkCnt[c][e];
            roff[e + 1] = roff[e] + ((rc + 127) & ~127);
            qoff[e + 1] = qoff[e] + ((qc + 127) & ~127);
        }
        for (int e = 0; e <= NELEM; e++) { g_Roff[e] = roff[e]; g_Qoff[e] = qoff[e]; }
        for (int e = 0; e < NELEM; e++) {
            int run = 0;
            for (int c = 0; c < NCH_R; c++) { g_chunkBase[c][e] = run; run += g_chunkCnt[c][e]; }
            run = 0;
            for (int c = NCH_R; c < NCH; c++) { g_chunkBase[c][e] = run; run += g_chunkCnt[c][e]; }
        }
        int n1 = 0;
        for (int e = 0; e < NELEM; e++) {
            const int qt = (qoff[e + 1] - qoff[e]) / 128;
            const int rt = (roff[e + 1] - roff[e]) / 128;
            for (int jt = 0; jt < qt; jt++)
                for (int it = 0; it < rt; it++)
                    g_T1[n1++] = make_int2(qoff[e] + jt * 128, roff[e] + it * 128);
        }
        g_nT1 = n1;
        int n2 = 0;
        for (int e = 0; e < NELEM; e++) {
            const int qt = (qoff[e + 1] - qoff[e]) / 128;
            for (int jt = 0; jt < qt; jt++)
                g_T2[n2++] = make_int2(qoff[e] + jt * 128, e);
        }
        g_nT2 = n2;
    }
}

// ---------------------------------------------------------------------------
// meta pass 3: slot assignment — intra-chunk prefix scan (12 CTAs in parallel)
// ---------------------------------------------------------------------------
__global__ void meta_assign(const int* __restrict__ Zr, const int* __restrict__ Zq) {
    __shared__ uint4 scan[1024];
    const int c = blockIdx.x, tid = threadIdx.x;
    const bool isRef = (c < NCH_R);
    const int idx = isRef ? c * 1024 + tid : (c - NCH_R) * 1024 + tid;
    const int z = isRef ? Zr[idx] : Zq[idx];

    scan[tid] = make_uint4(z == 0, z == 1, z == 2, z == 3);
    __syncthreads();
    for (int off = 1; off < 1024; off <<= 1) {
        uint4 add = make_uint4(0, 0, 0, 0);
        if (tid >= off) add = scan[tid - off];
        __syncthreads();
        uint4 cur = scan[tid];
        cur.x += add.x; cur.y += add.y; cur.z += add.z; cur.w += add.w;
        scan[tid] = cur;
        __syncthreads();
    }
    uint4 incl = scan[tid];
    const int rank = (int)(z == 0 ? incl.x : z == 1 ? incl.y : z == 2 ? incl.z : incl.w) - 1;
    if (isRef) {
        const int slot = g_Roff[z] + g_chunkBase[c][z] + rank;
        g_rslot2orig[slot] = idx;
    } else {
        const int slot = g_Qoff[z] + g_chunkBase[c][z] + rank;
        g_qslot2orig[slot] = idx;
        g_qinv[idx] = slot;
    }
}

// ---------------------------------------------------------------------------
// gather / convert kernels
// ---------------------------------------------------------------------------
__global__ void gather_X(const float* __restrict__ X) {
    const int row = blockIdx.x;
    const int orig = g_rslot2orig[row];
    __half2* dst = (__half2*)(g_X16g + (size_t)row * DFEAT);
    if (orig < 0) {
        const __half2 z = __halves2half2(__float2half(0.f), __float2half(0.f));
        for (int cc = threadIdx.x; cc < DFEAT / 2; cc += 256) dst[cc] = z;
    } else {
        const float2* src = (const float2*)(X + (size_t)orig * DFEAT);
        for (int cc = threadIdx.x; cc < DFEAT / 2; cc += 256) {
            float2 v = src[cc];
            dst[cc] = __halves2half2(__float2half(v.x), __float2half(v.y));
        }
    }
}

__global__ void gather_D(const float* __restrict__ D) {
    const int row = blockIdx.x;
    const int orig = g_qslot2orig[row];
    __half2* dst = (__half2*)(g_D16g + (size_t)row * DFEAT);
    if (orig < 0) {
        const __half2 z = __halves2half2(__float2half(0.f), __float2half(0.f));
        for (int cc = threadIdx.x; cc < DFEAT / 2; cc += 256) dst[cc] = z;
    } else {
        const float2* src = (const float2*)(D + (size_t)orig * DFEAT);
        for (int cc = threadIdx.x; cc < DFEAT / 2; cc += 256) {
            float2 v = src[cc];
            dst[cc] = __halves2half2(__float2half(v.x), __float2half(v.y));
        }
    }
}

__global__ void gather_A(const float* __restrict__ A) {
    const int i = blockIdx.x * blockDim.x + threadIdx.x;
    if (i < PDIM * RTOTP) {
        const int p = i / RTOTP, s = i - p * RTOTP;
        const int orig = g_rslot2orig[s];
        const float v = (orig < 0) ? 0.f : A[(size_t)p * NREF + orig];
        g_A16g[i] = __float2half(v);
    }
}

// ---------------------------------------------------------------------------
// shared GEMM machinery
// ---------------------------------------------------------------------------
__device__ __forceinline__ void load_tile(unsigned sbuf, const void* src_,
                                          int rowBase, int K, int kOff, int tid) {
    const char* src = (const char*)src_;
    const int row = tid >> 1;
    const int ch0 = (tid & 1) * 2;
    const char* g = src + ((size_t)(rowBase + row) * K + kOff) * 2 + ch0 * 16;
    const int sw = (row >> 1) & 3;
    const unsigned s0 = sbuf + row * 64 + (((ch0)     ^ sw) << 4);
    const unsigned s1 = sbuf + row * 64 + (((ch0 + 1) ^ sw) << 4);
    asm volatile("cp.async.cg.shared.global [%0], [%1], 16;\n\t"
                 "cp.async.cg.shared.global [%2], [%3], 16;"
                 :: "r"(s0), "l"(g), "r"(s1), "l"(g + 16));
}

__device__ __forceinline__ void mma16h(float* c, const unsigned* a, unsigned b0, unsigned b1) {
    asm volatile(
        "mma.sync.aligned.m16n8k16.row.col.f32.f16.f16.f32 "
        "{%0,%1,%2,%3}, {%4,%5,%6,%7}, {%8,%9}, {%0,%1,%2,%3};"
        : "+f"(c[0]), "+f"(c[1]), "+f"(c[2]), "+f"(c[3])
        : "r"(a[0]), "r"(a[1]), "r"(a[2]), "r"(a[3]), "r"(b0), "r"(b1));
}

#define LDSM4(r, addr)                                                           \
    asm volatile("ldmatrix.sync.aligned.m8n8.x4.shared.b16 {%0,%1,%2,%3}, [%4];" \
                 : "=r"((r)[0]), "=r"((r)[1]), "=r"((r)[2]), "=r"((r)[3])        \
                 : "r"(addr))

__device__ __forceinline__ unsigned sw_addr(int row, int ch) {
    return row * 64 + ((ch ^ ((row >> 1) & 3)) << 4);
}

// ---------------------------------------------------------------------------
// GEMM1 (grouped, 1-term fp16): Ktp[jslot, islot] = (D16[j].X16[i])^expK
// ---------------------------------------------------------------------------
__global__ __launch_bounds__(256, 2) void gemm1_mma(const int* __restrict__ expKp) {
    if (blockIdx.x >= g_nT1) return;
    extern __shared__ char dynsm[];
    const int tid = threadIdx.x, lane = tid & 31, wid = tid >> 5;
    const int warpM = wid & 3, warpN = wid >> 2;
    const int2 t = g_T1[blockIdx.x];
    const int jBase = t.x, iBase = t.y;

    float c[2][8][4];
#pragma unroll
    for (int i = 0; i < 2; i++)
#pragma unroll
        for (int j = 0; j < 8; j++)
#pragma unroll
            for (int k = 0; k < 4; k++) c[i][j][k] = 0.0f;

    unsigned st[NSTAGE][2];
#pragma unroll
    for (int s = 0; s < NSTAGE; s++)
#pragma unroll
        for (int tt = 0; tt < 2; tt++)
            st[s][tt] = sm32(dynsm + s * G1_STAGE + tt * TILE_B);

#pragma unroll
    for (int s = 0; s < 2; s++) {
        load_tile(st[s][0], g_D16g, jBase, DFEAT, s * 32, tid);
        load_tile(st[s][1], g_X16g, iBase, DFEAT, s * 32, tid);
        asm volatile("cp.async.commit_group;" ::: "memory");
    }

    const int NITER = DFEAT / 32;       // 16
    for (int it = 0; it < NITER; it++) {
        asm volatile("cp.async.wait_group 1;" ::: "memory");
        __syncthreads();
        if (it + 2 < NITER) {
            const int s = (it + 2) % NSTAGE, kOff = (it + 2) * 32;
            load_tile(st[s][0], g_D16g, jBase, DFEAT, kOff, tid);
            load_tile(st[s][1], g_X16g, iBase, DFEAT, kOff, tid);
        }
        asm volatile("cp.async.commit_group;" ::: "memory");
        const int b = it % NSTAGE;

#pragma unroll
        for (int kk = 0; kk < 32; kk += 16) {
            unsigned a[2][4];
#pragma unroll
            for (int mi = 0; mi < 2; mi++) {
                const int r  = warpM * 32 + mi * 16 + (lane & 15);
                const int ch = (kk >> 3) + ((lane >> 4) & 1);
                LDSM4(a[mi], st[b][0] + sw_addr(r, ch));
            }
#pragma unroll
            for (int g = 0; g < 4; g++) {
                const int rb  = warpN * 64 + g * 16 + (lane & 7) + ((lane >> 4) & 1) * 8;
                const int chb = (kk >> 3) + ((lane >> 3) & 1);
                unsigned bx[4];
                LDSM4(bx, st[b][1] + sw_addr(rb, chb));
                mma16h(c[0][2 * g],     a[0], bx[0], bx[1]);
                mma16h(c[0][2 * g + 1], a[0], bx[2], bx[3]);
                mma16h(c[1][2 * g],     a[1], bx[0], bx[1]);
                mma16h(c[1][2 * g + 1], a[1], bx[2], bx[3]);
            }
        }
    }

    // epilogue: pow only, fp16 store to padded-permuted K^T
    const int e = expKp[0];
#pragma unroll
    for (int mi = 0; mi < 2; mi++) {
        const int r0 = jBase + warpM * 32 + mi * 16 + (lane >> 2);
        const size_t ro0 = (size_t)r0 * RTOTP, ro1 = (size_t)(r0 + 8) * RTOTP;
#pragma unroll
        for (int ni = 0; ni < 8; ni++) {
            const int colL = warpN * 64 + ni * 8 + 2 * (lane & 3);
            float v0 = c[mi][ni][0], v1 = c[mi][ni][1];
            float v2 = c[mi][ni][2], v3 = c[mi][ni][3];
            float p0 = 1.f, p1 = 1.f, p2 = 1.f, p3 = 1.f;
            for (int t2 = 0; t2 < e; t2++) { p0 *= v0; p1 *= v1; p2 *= v2; p3 *= v3; }
            const size_t cg = (size_t)iBase + colL;
            *(__half2*)(g_Ktp + ro0 + cg) = __halves2half2(__float2half(p0), __float2half(p1));
            *(__half2*)(g_Ktp + ro1 + cg) = __halves2half2(__float2half(p2), __float2half(p3));
        }
    }
}

// ---------------------------------------------------------------------------
// GEMM2 (grouped, 1-term fp16, split-K=2 per element)
// ---------------------------------------------------------------------------
__global__ __launch_bounds__(256, 2) void gemm2_mma(void) {
    if (blockIdx.x >= g_nT2) return;
    extern __shared__ char dynsm[];
    const int tid = threadIdx.x, lane = tid & 31, wid = tid >> 5;
    const int warpM = wid & 3, warpN = wid >> 2;
    const int2 t = g_T2[blockIdx.x];
    const int jBase = t.x, elem = t.y;
    const int pBase = blockIdx.y * 128;
    const int rbeg = g_Roff[elem];
    const int half = (g_Roff[elem + 1] - rbeg) >> 1;
    const int kBase = rbeg + blockIdx.z * half;
    const int NITER = half / 32;
    float* P = g_P + (size_t)blockIdx.z * PDIM * QTOTP;

    float c[2][8][4];
#pragma unroll
    for (int i = 0; i < 2; i++)
#pragma unroll
        for (int j = 0; j < 8; j++)
#pragma unroll
            for (int k = 0; k < 4; k++) c[i][j][k] = 0.0f;

    unsigned st[NSTAGE][2];
#pragma unroll
    for (int s = 0; s < NSTAGE; s++)
#pragma unroll
        for (int tt = 0; tt < 2; tt++)
            st[s][tt] = sm32(dynsm + s * G2_STAGE + tt * TILE_B);

#pragma unroll
    for (int s = 0; s < 2; s++) {
        if (s < NITER) {
            const int kOff = kBase + s * 32;
            load_tile(st[s][0], g_A16g, pBase, RTOTP, kOff, tid);
            load_tile(st[s][1], g_Ktp, jBase, RTOTP, kOff, tid);
        }
        asm volatile("cp.async.commit_group;" ::: "memory");
    }

    for (int it = 0; it < NITER; it++) {
        asm volatile("cp.async.wait_group 1;" ::: "memory");
        __syncthreads();
        if (it + 2 < NITER) {
            const int s = (it + 2) % NSTAGE, kOff = kBase + (it + 2) * 32;
            load_tile(st[s][0], g_A16g, pBase, RTOTP, kOff, tid);
            load_tile(st[s][1], g_Ktp, jBase, RTOTP, kOff, tid);
        }
        asm volatile("cp.async.commit_group;" ::: "memory");
        const int b = it % NSTAGE;

#pragma unroll
        for (int kk = 0; kk < 32; kk += 16) {
            unsigned a[2][4];
#pragma unroll
            for (int mi = 0; mi < 2; mi++) {
                const int r  = warpM * 32 + mi * 16 + (lane & 15);
                const int ch = (kk >> 3) + ((lane >> 4) & 1);
                LDSM4(a[mi], st[b][0] + sw_addr(r, ch));
            }
#pragma unroll
            for (int g = 0; g < 4; g++) {
                const int rb  = warpN * 64 + g * 16 + (lane & 7) + ((lane >> 4) & 1) * 8;
                const int chb = (kk >> 3) + ((lane >> 3) & 1);
                unsigned bh[4];
                LDSM4(bh, st[b][1] + sw_addr(rb, chb));
                mma16h(c[0][2 * g],     a[0], bh[0], bh[1]);
                mma16h(c[0][2 * g + 1], a[0], bh[2], bh[3]);
                mma16h(c[1][2 * g],     a[1], bh[0], bh[1]);
                mma16h(c[1][2 * g + 1], a[1], bh[2], bh[3]);
            }
        }
    }

#pragma unroll
    for (int mi = 0; mi < 2; mi++) {
        const int r0 = pBase + warpM * 32 + mi * 16 + (lane >> 2);
        const size_t ro0 = (size_t)r0 * QTOTP, ro1 = (size_t)(r0 + 8) * QTOTP;
#pragma unroll
        for (int ni = 0; ni < 8; ni++) {
            const int col = jBase + warpN * 64 + ni * 8 + 2 * (lane & 3);
            *(float2*)(P + ro0 + col) = make_float2(c[mi][ni][0], c[mi][ni][1]);
            *(float2*)(P + ro1 + col) = make_float2(c[mi][ni][2], c[mi][ni][3]);
        }
    }
}

// Reduce split-K partials + unpermute columns into the output.
__global__ void reduceY(float* __restrict__ Y) {
    const int i = blockIdx.x * blockDim.x + threadIdx.x;
    if (i < PDIM * NIN) {
        const int p = i / NIN, j = i - p * NIN;
        const int s = g_qinv[j];
        const size_t off = (size_t)p * QTOTP + s;
        Y[i] = g_P[off] + g_P[(size_t)PDIM * QTOTP + off];
    }
}

extern "C" void kernel_launch(void* const* d_in, const int* in_sizes, int n_in,
                              void* d_out, int out_size) {
    const float* Alpha = (const float*)d_in[0];
    const float* X_ref = (const float*)d_in[1];
    const float* desc  = (const float*)d_in[2];
    const int*   Z_ref = (const int*)d_in[3];
    const int*   Z     = (const int*)d_in[4];
    const int*   expK  = (const int*)d_in[5];
    float* Y = (float*)d_out;

    cudaFuncSetAttribute(gemm1_mma, cudaFuncAttributeMaxDynamicSharedMemorySize, G1_SMEM);
    cudaFuncSetAttribute(gemm2_mma, cudaFuncAttributeMaxDynamicSharedMemorySize, G2_SMEM);

    meta_hist<<<NCH, 1024>>>(Z_ref, Z);
    meta_off<<<1, 1024>>>();
    meta_assign<<<NCH, 1024>>>(Z_ref, Z);
    gather_X<<<RTOTP, 256>>>(X_ref);
    gather_D<<<QTOTP, 256>>>(desc);
    gather_A<<<(PDIM * RTOTP + 255) / 256, 256>>>(Alpha);

    gemm1_mma<<<MAXT1, 256, G1_SMEM>>>(expK);
    gemm2_mma<<<dim3(QTOTP / 128, PDIM / 128, 2), 256, G2_SMEM>>>();
    reduceY<<<(PDIM * NIN + 255) / 256, 256>>>(Y);
}

// round 17
// speedup vs baseline: 9.3428x; 1.0740x over previous
#include <cuda_runtime.h>
#include <cuda_fp16.h>

#define NREF  4096
#define NIN   8192
#define DFEAT 512
#define PDIM  256
#define NELEM 4

#define RTOTP 4608
#define QTOTP 8704
#define MAXT1 2560
#define NCH_R 4
#define NCH_Q 8
#define NCH   (NCH_R + NCH_Q)
#define A_CTAS ((PDIM * RTOTP) / 2048)      // 576

#define TILE_B   8192
#define NSTAGE   3
#define G1_STAGE (2 * TILE_B)
#define G1_SMEM  (NSTAGE * G1_STAGE + 512)
#define G2_STAGE (2 * TILE_B)
#define G2_SMEM  (NSTAGE * G2_STAGE + 512)

// ---------------- scratch (device globals; device-code refs only) ----------
__device__ __half g_X16g[RTOTP * DFEAT];
__device__ __half g_D16g[(size_t)QTOTP * DFEAT];
__device__ __half g_A16g[PDIM * RTOTP];
__device__ __half g_Ktp[(size_t)QTOTP * RTOTP];
__device__ float  g_P[2 * PDIM * QTOTP];
__device__ int  g_rslot2orig[RTOTP];
__device__ int  g_qslot2orig[QTOTP];
__device__ int  g_qinv[NIN];
__device__ int  g_Roff[NELEM + 1];
__device__ int  g_chunkCnt[NCH][NELEM];
__device__ int  g_nT1;
__device__ int2 g_T1[MAXT1];
__device__ int  g_nT2;
__device__ int2 g_T2[80];

__device__ __forceinline__ unsigned sm32(const void* p) {
    unsigned r;
    asm("{.reg .u64 t; cvta.to.shared.u64 t, %1; cvt.u32.u64 %0, t;}" : "=r"(r) : "l"(p));
    return r;
}

// ---------------------------------------------------------------------------
// meta pass 1: slot-map init + per-chunk histograms (12 CTAs)
// ---------------------------------------------------------------------------
__global__ void meta_hist(const int* __restrict__ Zr, const int* __restrict__ Zq) {
    __shared__ int cnt[NELEM];
    const int c = blockIdx.x, tid = threadIdx.x;
    const int gid = c * 1024 + tid;
    if (gid < RTOTP) g_rslot2orig[gid] = -1;
    if (gid < QTOTP) g_qslot2orig[gid] = -1;
    if (tid < NELEM) cnt[tid] = 0;
    __syncthreads();
    const int z = (c < NCH_R) ? Zr[c * 1024 + tid] : Zq[(c - NCH_R) * 1024 + tid];
    atomicAdd(&cnt[z], 1);
    __syncthreads();
    if (tid < NELEM) g_chunkCnt[c][tid] = cnt[tid];
}

// ---------------------------------------------------------------------------
// meta pass 2: offsets (recomputed per CTA) + scan + slot assign + tables
// ---------------------------------------------------------------------------
__global__ void meta_assign(const int* __restrict__ Zr, const int* __restrict__ Zq) {
    __shared__ uint4 scan[1024];
    __shared__ int roff[NELEM + 1], qoff[NELEM + 1], mybase[NELEM];
    const int c = blockIdx.x, tid = threadIdx.x;
    const bool isRef = (c < NCH_R);

    if (tid == 0) {
        roff[0] = 0; qoff[0] = 0;
        for (int e = 0; e < NELEM; e++) {
            int rc = 0, qc = 0;
            for (int k = 0; k < NCH_R; k++) rc += g_chunkCnt[k][e];
            for (int k = NCH_R; k < NCH; k++) qc += g_chunkCnt[k][e];
            roff[e + 1] = roff[e] + ((rc + 127) & ~127);
            qoff[e + 1] = qoff[e] + ((qc + 127) & ~127);
        }
        for (int e = 0; e < NELEM; e++) {
            int run = 0;
            if (isRef) { for (int k = 0;     k < c; k++) run += g_chunkCnt[k][e]; }
            else       { for (int k = NCH_R; k < c; k++) run += g_chunkCnt[k][e]; }
            mybase[e] = run;
        }
        if (c == 0) {
            for (int e = 0; e <= NELEM; e++) g_Roff[e] = roff[e];
            int n1 = 0;
            for (int e = 0; e < NELEM; e++) {
                const int qt = (qoff[e + 1] - qoff[e]) / 128;
                const int rt = (roff[e + 1] - roff[e]) / 128;
                for (int jt = 0; jt < qt; jt++)
                    for (int it = 0; it < rt; it++)
                        g_T1[n1++] = make_int2(qoff[e] + jt * 128, roff[e] + it * 128);
            }
            g_nT1 = n1;
            int n2 = 0;
            for (int e = 0; e < NELEM; e++) {
                const int qt = (qoff[e + 1] - qoff[e]) / 128;
                for (int jt = 0; jt < qt; jt++)
                    g_T2[n2++] = make_int2(qoff[e] + jt * 128, e);
            }
            g_nT2 = n2;
        }
    }

    const int idx = isRef ? c * 1024 + tid : (c - NCH_R) * 1024 + tid;
    const int z = isRef ? Zr[idx] : Zq[idx];
    scan[tid] = make_uint4(z == 0, z == 1, z == 2, z == 3);
    __syncthreads();
    for (int off = 1; off < 1024; off <<= 1) {
        uint4 add = make_uint4(0, 0, 0, 0);
        if (tid >= off) add = scan[tid - off];
        __syncthreads();
        uint4 cur = scan[tid];
        cur.x += add.x; cur.y += add.y; cur.z += add.z; cur.w += add.w;
        scan[tid] = cur;
        __syncthreads();
    }
    uint4 incl = scan[tid];
    const int rank = (int)(z == 0 ? incl.x : z == 1 ? incl.y : z == 2 ? incl.z : incl.w) - 1;
    if (isRef) {
        g_rslot2orig[roff[z] + mybase[z] + rank] = idx;
    } else {
        const int slot = qoff[z] + mybase[z] + rank;
        g_qslot2orig[slot] = idx;
        g_qinv[idx] = slot;
    }
}

// ---------------------------------------------------------------------------
// fused gather: X rows | D rows | A chunks
// ---------------------------------------------------------------------------
__global__ void gather_all(const float* __restrict__ X, const float* __restrict__ D,
                           const float* __restrict__ A) {
    const int b = blockIdx.x, tid = threadIdx.x;
    const __half2 z2 = __halves2half2(__float2half(0.f), __float2half(0.f));
    if (b < RTOTP) {
        const int orig = g_rslot2orig[b];
        __half2* dst = (__half2*)(g_X16g + (size_t)b * DFEAT);
        if (orig < 0) {
            for (int cc = tid; cc < DFEAT / 2; cc += 256) dst[cc] = z2;
        } else {
            const float2* src = (const float2*)(X + (size_t)orig * DFEAT);
            for (int cc = tid; cc < DFEAT / 2; cc += 256) {
                float2 v = src[cc];
                dst[cc] = __halves2half2(__float2half(v.x), __float2half(v.y));
            }
        }
    } else if (b < RTOTP + QTOTP) {
        const int row = b - RTOTP;
        const int orig = g_qslot2orig[row];
        __half2* dst = (__half2*)(g_D16g + (size_t)row * DFEAT);
        if (orig < 0) {
            for (int cc = tid; cc < DFEAT / 2; cc += 256) dst[cc] = z2;
        } else {
            const float2* src = (const float2*)(D + (size_t)orig * DFEAT);
            for (int cc = tid; cc < DFEAT / 2; cc += 256) {
                float2 v = src[cc];
                dst[cc] = __halves2half2(__float2half(v.x), __float2half(v.y));
            }
        }
    } else {
        const int base = (b - RTOTP - QTOTP) * 2048;
#pragma unroll
        for (int k = 0; k < 8; k++) {
            const int i = base + k * 256 + tid;
            const int p = i / RTOTP, s = i - p * RTOTP;
            const int orig = g_rslot2orig[s];
            const float v = (orig < 0) ? 0.f : A[(size_t)p * NREF + orig];
            g_A16g[i] = __float2half(v);
        }
    }
}

// ---------------------------------------------------------------------------
// shared GEMM machinery
// ---------------------------------------------------------------------------
__device__ __forceinline__ void load_tile(unsigned sbuf, const void* src_,
                                          int rowBase, int K, int kOff, int tid) {
    const char* src = (const char*)src_;
    const int row = tid >> 1;
    const int ch0 = (tid & 1) * 2;
    const char* g = src + ((size_t)(rowBase + row) * K + kOff) * 2 + ch0 * 16;
    const int sw = (row >> 1) & 3;
    const unsigned s0 = sbuf + row * 64 + (((ch0)     ^ sw) << 4);
    const unsigned s1 = sbuf + row * 64 + (((ch0 + 1) ^ sw) << 4);
    asm volatile("cp.async.cg.shared.global [%0], [%1], 16;\n\t"
                 "cp.async.cg.shared.global [%2], [%3], 16;"
                 :: "r"(s0), "l"(g), "r"(s1), "l"(g + 16));
}

__device__ __forceinline__ void mma16h(float* c, const unsigned* a, unsigned b0, unsigned b1) {
    asm volatile(
        "mma.sync.aligned.m16n8k16.row.col.f32.f16.f16.f32 "
        "{%0,%1,%2,%3}, {%4,%5,%6,%7}, {%8,%9}, {%0,%1,%2,%3};"
        : "+f"(c[0]), "+f"(c[1]), "+f"(c[2]), "+f"(c[3])
        : "r"(a[0]), "r"(a[1]), "r"(a[2]), "r"(a[3]), "r"(b0), "r"(b1));
}

#define LDSM4(r, addr)                                                           \
    asm volatile("ldmatrix.sync.aligned.m8n8.x4.shared.b16 {%0,%1,%2,%3}, [%4];" \
                 : "=r"((r)[0]), "=r"((r)[1]), "=r"((r)[2]), "=r"((r)[3])        \
                 : "r"(addr))

__device__ __forceinline__ unsigned sw_addr(int row, int ch) {
    return row * 64 + ((ch ^ ((row >> 1) & 3)) << 4);
}

// ---------------------------------------------------------------------------
// GEMM1 (grouped, 1-term fp16): Ktp[jslot, islot] = (D16[j].X16[i])^expK
// ---------------------------------------------------------------------------
__global__ __launch_bounds__(256, 2) void gemm1_mma(const int* __restrict__ expKp) {
    if (blockIdx.x >= g_nT1) return;
    extern __shared__ char dynsm[];
    const int tid = threadIdx.x, lane = tid & 31, wid = tid >> 5;
    const int warpM = wid & 3, warpN = wid >> 2;
    const int2 t = g_T1[blockIdx.x];
    const int jBase = t.x, iBase = t.y;

    float c[2][8][4];
#pragma unroll
    for (int i = 0; i < 2; i++)
#pragma unroll
        for (int j = 0; j < 8; j++)
#pragma unroll
            for (int k = 0; k < 4; k++) c[i][j][k] = 0.0f;

    unsigned st[NSTAGE][2];
#pragma unroll
    for (int s = 0; s < NSTAGE; s++)
#pragma unroll
        for (int tt = 0; tt < 2; tt++)
            st[s][tt] = sm32(dynsm + s * G1_STAGE + tt * TILE_B);

#pragma unroll
    for (int s = 0; s < 2; s++) {
        load_tile(st[s][0], g_D16g, jBase, DFEAT, s * 32, tid);
        load_tile(st[s][1], g_X16g, iBase, DFEAT, s * 32, tid);
        asm volatile("cp.async.commit_group;" ::: "memory");
    }

    const int NITER = DFEAT / 32;       // 16
    for (int it = 0; it < NITER; it++) {
        asm volatile("cp.async.wait_group 1;" ::: "memory");
        __syncthreads();
        if (it + 2 < NITER) {
            const int s = (it + 2) % NSTAGE, kOff = (it + 2) * 32;
            load_tile(st[s][0], g_D16g, jBase, DFEAT, kOff, tid);
            load_tile(st[s][1], g_X16g, iBase, DFEAT, kOff, tid);
        }
        asm volatile("cp.async.commit_group;" ::: "memory");
        const int b = it % NSTAGE;

#pragma unroll
        for (int kk = 0; kk < 32; kk += 16) {
            unsigned a[2][4];
#pragma unroll
            for (int mi = 0; mi < 2; mi++) {
                const int r  = warpM * 32 + mi * 16 + (lane & 15);
                const int ch = (kk >> 3) + ((lane >> 4) & 1);
                LDSM4(a[mi], st[b][0] + sw_addr(r, ch));
            }
#pragma unroll
            for (int g = 0; g < 4; g++) {
                const int rb  = warpN * 64 + g * 16 + (lane & 7) + ((lane >> 4) & 1) * 8;
                const int chb = (kk >> 3) + ((lane >> 3) & 1);
                unsigned bx[4];
                LDSM4(bx, st[b][1] + sw_addr(rb, chb));
                mma16h(c[0][2 * g],     a[0], bx[0], bx[1]);
                mma16h(c[0][2 * g + 1], a[0], bx[2], bx[3]);
                mma16h(c[1][2 * g],     a[1], bx[0], bx[1]);
                mma16h(c[1][2 * g + 1], a[1], bx[2], bx[3]);
            }
        }
    }

    const int e = expKp[0];
#pragma unroll
    for (int mi = 0; mi < 2; mi++) {
        const int r0 = jBase + warpM * 32 + mi * 16 + (lane >> 2);
        const size_t ro0 = (size_t)r0 * RTOTP, ro1 = (size_t)(r0 + 8) * RTOTP;
#pragma unroll
        for (int ni = 0; ni < 8; ni++) {
            const int colL = warpN * 64 + ni * 8 + 2 * (lane & 3);
            float v0 = c[mi][ni][0], v1 = c[mi][ni][1];
            float v2 = c[mi][ni][2], v3 = c[mi][ni][3];
            float p0 = 1.f, p1 = 1.f, p2 = 1.f, p3 = 1.f;
            for (int t2 = 0; t2 < e; t2++) { p0 *= v0; p1 *= v1; p2 *= v2; p3 *= v3; }
            const size_t cg = (size_t)iBase + colL;
            *(__half2*)(g_Ktp + ro0 + cg) = __halves2half2(__float2half(p0), __float2half(p1));
            *(__half2*)(g_Ktp + ro1 + cg) = __halves2half2(__float2half(p2), __float2half(p3));
        }
    }
}

// ---------------------------------------------------------------------------
// GEMM2 (grouped, 1-term fp16, split-K=2 per element)
// ---------------------------------------------------------------------------
__global__ __launch_bounds__(256, 2) void gemm2_mma(void) {
    if (blockIdx.x >= g_nT2) return;
    extern __shared__ char dynsm[];
    const int tid = threadIdx.x, lane = tid & 31, wid = tid >> 5;
    const int warpM = wid & 3, warpN = wid >> 2;
    const int2 t = g_T2[blockIdx.x];
    const int jBase = t.x, elem = t.y;
    const int pBase = blockIdx.y * 128;
    const int rbeg = g_Roff[elem];
    const int half = (g_Roff[elem + 1] - rbeg) >> 1;
    const int kBase = rbeg + blockIdx.z * half;
    const int NITER = half / 32;
    float* P = g_P + (size_t)blockIdx.z * PDIM * QTOTP;

    float c[2][8][4];
#pragma unroll
    for (int i = 0; i < 2; i++)
#pragma unroll
        for (int j = 0; j < 8; j++)
#pragma unroll
            for (int k = 0; k < 4; k++) c[i][j][k] = 0.0f;

    unsigned st[NSTAGE][2];
#pragma unroll
    for (int s = 0; s < NSTAGE; s++)
#pragma unroll
        for (int tt = 0; tt < 2; tt++)
            st[s][tt] = sm32(dynsm + s * G2_STAGE + tt * TILE_B);

#pragma unroll
    for (int s = 0; s < 2; s++) {
        if (s < NITER) {
            const int kOff = kBase + s * 32;
            load_tile(st[s][0], g_A16g, pBase, RTOTP, kOff, tid);
            load_tile(st[s][1], g_Ktp, jBase, RTOTP, kOff, tid);
        }
        asm volatile("cp.async.commit_group;" ::: "memory");
    }

    for (int it = 0; it < NITER; it++) {
        asm volatile("cp.async.wait_group 1;" ::: "memory");
        __syncthreads();
        if (it + 2 < NITER) {
            const int s = (it + 2) % NSTAGE, kOff = kBase + (it + 2) * 32;
            load_tile(st[s][0], g_A16g, pBase, RTOTP, kOff, tid);
            load_tile(st[s][1], g_Ktp, jBase, RTOTP, kOff, tid);
        }
        asm volatile("cp.async.commit_group;" ::: "memory");
        const int b = it % NSTAGE;

#pragma unroll
        for (int kk = 0; kk < 32; kk += 16) {
            unsigned a[2][4];
#pragma unroll
            for (int mi = 0; mi < 2; mi++) {
                const int r  = warpM * 32 + mi * 16 + (lane & 15);
                const int ch = (kk >> 3) + ((lane >> 4) & 1);
                LDSM4(a[mi], st[b][0] + sw_addr(r, ch));
            }
#pragma unroll
            for (int g = 0; g < 4; g++) {
                const int rb  = warpN * 64 + g * 16 + (lane & 7) + ((lane >> 4) & 1) * 8;
                const int chb = (kk >> 3) + ((lane >> 3) & 1);
                unsigned bh[4];
                LDSM4(bh, st[b][1] + sw_addr(rb, chb));
                mma16h(c[0][2 * g],     a[0], bh[0], bh[1]);
                mma16h(c[0][2 * g + 1], a[0], bh[2], bh[3]);
                mma16h(c[1][2 * g],     a[1], bh[0], bh[1]);
                mma16h(c[1][2 * g + 1], a[1], bh[2], bh[3]);
            }
        }
    }

#pragma unroll
    for (int mi = 0; mi < 2; mi++) {
        const int r0 = pBase + warpM * 32 + mi * 16 + (lane >> 2);
        const size_t ro0 = (size_t)r0 * QTOTP, ro1 = (size_t)(r0 + 8) * QTOTP;
#pragma unroll
        for (int ni = 0; ni < 8; ni++) {
            const int col = jBase + warpN * 64 + ni * 8 + 2 * (lane & 3);
            *(float2*)(P + ro0 + col) = make_float2(c[mi][ni][0], c[mi][ni][1]);
            *(float2*)(P + ro1 + col) = make_float2(c[mi][ni][2], c[mi][ni][3]);
        }
    }
}

// Reduce split-K partials + unpermute columns into the output.
__global__ void reduceY(float* __restrict__ Y) {
    const int i = blockIdx.x * blockDim.x + threadIdx.x;
    if (i < PDIM * NIN) {
        const int p = i / NIN, j = i - p * NIN;
        const int s = g_qinv[j];
        const size_t off = (size_t)p * QTOTP + s;
        Y[i] = g_P[off] + g_P[(size_t)PDIM * QTOTP + off];
    }
}

extern "C" void kernel_launch(void* const* d_in, const int* in_sizes, int n_in,
                              void* d_out, int out_size) {
    const float* Alpha = (const float*)d_in[0];
    const float* X_ref = (const float*)d_in[1];
    const float* desc  = (const float*)d_in[2];
    const int*   Z_ref = (const int*)d_in[3];
    const int*   Z     = (const int*)d_in[4];
    const int*   expK  = (const int*)d_in[5];
    float* Y = (float*)d_out;

    cudaFuncSetAttribute(gemm1_mma, cudaFuncAttributeMaxDynamicSharedMemorySize, G1_SMEM);
    cudaFuncSetAttribute(gemm2_mma, cudaFuncAttributeMaxDynamicSharedMemorySize, G2_SMEM);

    meta_hist<<<NCH, 1024>>>(Z_ref, Z);
    meta_assign<<<NCH, 1024>>>(Z_ref, Z);
    gather_all<<<RTOTP + QTOTP + A_CTAS, 256>>>(X_ref, desc, Alpha);

    gemm1_mma<<<MAXT1, 256, G1_SMEM>>>(expK);
    gemm2_mma<<<dim3(QTOTP / 128, PDIM / 128, 2), 256, G2_SMEM>>>();
    reduceY<<<(PDIM * NIN + 255) / 256, 256>>>(Y);
}